// round 8
// baseline (speedup 1.0000x reference)
#include <cuda_runtime.h>
#include <math.h>
#include <stdint.h>

#define BATCH 2
#define C 512
#define L 4096
#define NH 4
#define HD 128
#define GROUPS 32
#define CPG (C / GROUPS)   // 16
#define EPS 1e-5f

// ---------------- scratch (static device globals; no allocation) ----------------
__device__ uint4 g_qf[(size_t)BATCH * NH * 32 * 2048];   // 8 MB  Q A-frags
__device__ uint2 g_kf[(size_t)BATCH * NH * 64 * 2048];   // 8 MB  K B-frags (16KB per 64-key tile)
__device__ uint2 g_vf[(size_t)BATCH * NH * 64 * 2048];   // 8 MB  V B-frags (16KB per 64-key tile)
__device__ uint2 g_xnf[(size_t)BATCH * 512 * 32 * 32];   // 8 MB  xn B-frags
__device__ uint2 g_attf[(size_t)BATCH * 512 * 32 * 32];  // 8 MB  att B-frags
__device__ uint4 g_wqf[(size_t)96 * 32 * 32];            // 1.5MB w_qkv A-frags
__device__ uint4 g_wpf[(size_t)32 * 32 * 32];            // 0.5MB w_proj A-frags

__device__ __forceinline__ uint32_t smem_u32(const void* p) {
    uint32_t a;
    asm("{ .reg .u64 t; cvta.to.shared.u64 t, %1; cvt.u32.u64 %0, t; }" : "=r"(a) : "l"(p));
    return a;
}
__device__ __forceinline__ uint32_t pack_bf16x2(float lo, float hi) {
    uint32_t d;
    asm("cvt.rn.bf16x2.f32 %0, %1, %2;" : "=r"(d) : "f"(hi), "f"(lo));
    return d;
}
#define MMA_BF16(d, a, b) \
    asm volatile("mma.sync.aligned.m16n8k16.row.col.f32.bf16.bf16.f32 " \
                 "{%0,%1,%2,%3}, {%4,%5,%6,%7}, {%8,%9}, {%0,%1,%2,%3};" \
                 : "+f"((d)[0]), "+f"((d)[1]), "+f"((d)[2]), "+f"((d)[3]) \
                 : "r"((a).x), "r"((a).y), "r"((a).z), "r"((a).w), \
                   "r"((b).x), "r"((b).y))

__device__ __forceinline__ void cp16(uint32_t dst, const void* src) {
    asm volatile("cp.async.cg.shared.global [%0], [%1], 16;" :: "r"(dst), "l"(src));
}
#define CP_COMMIT() asm volatile("cp.async.commit_group;" ::: "memory")
#define CP_WAIT(n)  asm volatile("cp.async.wait_group %0;" :: "n"(n) : "memory")

// ---------------- GroupNorm fused with xn fragment packing ----------------
__global__ void __launch_bounds__(256) groupnorm_pack_kernel(const float* __restrict__ x,
                                                             const float* __restrict__ gw,
                                                             const float* __restrict__ gb,
                                                             uint2* __restrict__ Bf) {
    const int g = blockIdx.x, b = blockIdx.y;
    const int tid = threadIdx.x;
    const size_t base = ((size_t)b * C + g * CPG) * L;
    const int SPAN = CPG * L;
    const float* xr = x + base;
    const float4* x4 = (const float4*)xr;
    float s = 0.f, ss = 0.f;
    for (int i = tid; i < SPAN / 4; i += 256) {
        float4 v = x4[i];
        s  += v.x + v.y + v.z + v.w;
        ss += v.x * v.x + v.y * v.y + v.z * v.z + v.w * v.w;
    }
    __shared__ float rs[256], rss[256];
    rs[tid] = s; rss[tid] = ss;
    __syncthreads();
    for (int off = 128; off; off >>= 1) {
        if (tid < off) { rs[tid] += rs[tid + off]; rss[tid] += rss[tid + off]; }
        __syncthreads();
    }
    __shared__ float ga_s[CPG], be_s[CPG];
    if (tid < CPG) {
        float mean = rs[0] / SPAN;
        float var  = rss[0] / SPAN - mean * mean;
        float rstd = rsqrtf(var + EPS);
        float ga = gw[g * CPG + tid] * rstd;
        ga_s[tid] = ga;
        be_s[tid] = gb[g * CPG + tid] - mean * ga;
    }
    __syncthreads();

    uint2* dst = Bf + (size_t)b * 524288 + (size_t)g * 32;
    for (int i = tid; i < 16384; i += 256) {
        const int nt = i >> 5, lane = i & 31;
        const int gid = lane >> 2, tig = lane & 3;
        const int n = nt * 8 + gid;
        const int lc = 2 * tig;
        float v0 = xr[(size_t)lc * L + n]       * ga_s[lc]     + be_s[lc];
        float v1 = xr[(size_t)(lc + 1) * L + n] * ga_s[lc + 1] + be_s[lc + 1];
        float v8 = xr[(size_t)(lc + 8) * L + n] * ga_s[lc + 8] + be_s[lc + 8];
        float v9 = xr[(size_t)(lc + 9) * L + n] * ga_s[lc + 9] + be_s[lc + 9];
        uint2 o;
        o.x = pack_bf16x2(v0, v1);
        o.y = pack_bf16x2(v8, v9);
        dst[(size_t)nt * 1024 + lane] = o;
    }
}

// ---------------- weight packing ----------------
__global__ void __launch_bounds__(256) pack_w_kernel(const float* __restrict__ W,
                                                     uint4* __restrict__ Wf) {
    const int idx = blockIdx.x * 256 + threadIdx.x;
    const int blk = idx >> 5, lane = idx & 31;
    const int mt = blk >> 5, kt = blk & 31;
    const int gid = lane >> 2, tig = lane & 3;
    const float* r0 = W + (size_t)(mt * 16 + gid) * 512 + kt * 16;
    const float* r8 = r0 + 8 * 512;
    float2 a0 = *(const float2*)(r0 + 2 * tig);
    float2 a1 = *(const float2*)(r8 + 2 * tig);
    float2 a2 = *(const float2*)(r0 + 2 * tig + 8);
    float2 a3 = *(const float2*)(r8 + 2 * tig + 8);
    uint4 o;
    o.x = pack_bf16x2(a0.x, a0.y); o.y = pack_bf16x2(a1.x, a1.y);
    o.z = pack_bf16x2(a2.x, a2.y); o.w = pack_bf16x2(a3.x, a3.y);
    Wf[idx] = o;
}

// ---------------- QKV GEMM: 4-stage pipeline + fused q/k/v fragment epilogue ----------------
#define QKV_SMEM 66560   // max(4 x 16KB staging, 128x130 fp32 T)

__global__ void __launch_bounds__(256) gemm_qkv_kernel(const uint4* __restrict__ Af,
                                                       const uint2* __restrict__ Bf,
                                                       const float* __restrict__ bias,
                                                       uint4* __restrict__ qf,
                                                       uint2* __restrict__ kf,
                                                       uint2* __restrict__ vf) {
    extern __shared__ char dynsm[];
    const uint32_t sb = smem_u32(dynsm);
    float* T = (float*)dynsm;
    const int tid = threadIdx.x, w = tid >> 5, l = tid & 31;
    const int mi = w >> 1, nh = w & 1, gid = l >> 2, tig = l & 3;
    const int nb = blockIdx.x, mb = blockIdx.y, bz = blockIdx.z;
    Bf += (size_t)bz * 524288;

    auto issue = [&](int kc, int s) {
        #pragma unroll
        for (int j = 0; j < 2; j++) {
            const int e = tid + j * 256;
            const int bl = e >> 5, ln = e & 31;
            const int i = bl >> 1, ktl = bl & 1;
            cp16(sb + s * 16384 + e * 16,
                 (const char*)(Af + ((size_t)(mb * 8 + i) * 32 + kc * 2 + ktl) * 32 + ln));
        }
        #pragma unroll
        for (int j = 0; j < 2; j++) {
            const int f = tid + j * 256;
            const int bl = f >> 4, lp = f & 15;
            const int nt = bl >> 1, ktl = bl & 1;
            cp16(sb + s * 16384 + 8192 + bl * 256 + lp * 16,
                 (const char*)Bf + ((size_t)(nb * 16 + nt) * 32 + kc * 2 + ktl) * 256 + lp * 16);
        }
    };

    issue(0, 0); CP_COMMIT();
    issue(1, 1); CP_COMMIT();
    issue(2, 2); CP_COMMIT();
    float acc[2][8][4] = {};
    for (int t = 0; t < 16; t++) {
        if (t < 14)       { CP_WAIT(2); }
        else if (t == 14) { CP_WAIT(1); }
        else              { CP_WAIT(0); }
        __syncthreads();
        if (t + 3 < 16) { issue(t + 3, (t + 3) & 3); CP_COMMIT(); }
        const int s = t & 3;
        #pragma unroll
        for (int ktl = 0; ktl < 2; ktl++) {
            uint4 A0 = *(const uint4*)(dynsm + s * 16384 + (((mi * 2 + 0) * 2 + ktl) * 32 + l) * 16);
            uint4 A1 = *(const uint4*)(dynsm + s * 16384 + (((mi * 2 + 1) * 2 + ktl) * 32 + l) * 16);
            #pragma unroll
            for (int nt = 0; nt < 8; nt++) {
                uint2 B = *(const uint2*)(dynsm + s * 16384 + 8192 + (((nh * 8 + nt) * 2 + ktl) * 32 + l) * 8);
                MMA_BF16(acc[0][nt], A0, B);
                MMA_BF16(acc[1][nt], A1, B);
            }
        }
    }
    __syncthreads();   // all warps done with staging before T overwrites it

    const int sec = mb >> 2, h = mb & 3;
    const int bh = bz * NH + h;
    const float qs = (sec == 0) ? 0.08838834764831845f : 1.0f;

    #pragma unroll
    for (int r = 0; r < 2; r++) {
        const int m0 = mi * 32 + r * 16 + gid;
        const float b0v = bias[mb * 128 + m0], b8v = bias[mb * 128 + m0 + 8];
        #pragma unroll
        for (int nt = 0; nt < 8; nt++) {
            const int n0 = nh * 64 + nt * 8 + 2 * tig;
            T[m0 * 130 + n0]           = (acc[r][nt][0] + b0v) * qs;
            T[m0 * 130 + n0 + 1]       = (acc[r][nt][1] + b0v) * qs;
            T[(m0 + 8) * 130 + n0]     = (acc[r][nt][2] + b8v) * qs;
            T[(m0 + 8) * 130 + n0 + 1] = (acc[r][nt][3] + b8v) * qs;
        }
    }
    __syncthreads();

    if (sec == 0) {
        // Q A-frags: qf[(bh*32 + nb)*2048 + (mtb*8 + ktc)*32 + ln]
        uint4* dst = qf + ((size_t)bh * 32 + nb) * 2048;
        #pragma unroll
        for (int it = 0; it < 8; it++) {
            const int idx = tid + it * 256;
            const int blk = idx >> 5, ln = idx & 31;
            const int mtb = blk >> 3, ktc = blk & 7;
            const int g2 = ln >> 2, t2 = ln & 3;
            const int q = mtb * 16 + g2, c = ktc * 16 + 2 * t2;
            uint4 o;
            o.x = pack_bf16x2(T[c * 130 + q],           T[(c + 1) * 130 + q]);
            o.y = pack_bf16x2(T[c * 130 + q + 8],       T[(c + 1) * 130 + q + 8]);
            o.z = pack_bf16x2(T[(c + 8) * 130 + q],     T[(c + 9) * 130 + q]);
            o.w = pack_bf16x2(T[(c + 8) * 130 + q + 8], T[(c + 9) * 130 + q + 8]);
            dst[idx] = o;
        }
    } else if (sec == 1) {
        // K B-frags, 64-key-tile-contiguous: kf[bh*131072 + t64*2048 + (ktc*8 + ntb&7)*32 + ln]
        uint2* dst = kf + (size_t)bh * 131072;
        #pragma unroll
        for (int it = 0; it < 16; it++) {
            const int idx = tid + it * 256;
            const int blk = idx >> 5, ln = idx & 31;
            const int ktc = blk >> 4, ntb = blk & 15;
            const int g2 = ln >> 2, t2 = ln & 3;
            const int key = ntb * 8 + g2, c0 = ktc * 16 + 2 * t2;
            const int t64 = nb * 2 + (ntb >> 3);
            uint2 o;
            o.x = pack_bf16x2(T[c0 * 130 + key],       T[(c0 + 1) * 130 + key]);
            o.y = pack_bf16x2(T[(c0 + 8) * 130 + key], T[(c0 + 9) * 130 + key]);
            dst[(size_t)t64 * 2048 + (ktc * 8 + (ntb & 7)) * 32 + ln] = o;
        }
    } else {
        // V B-frags, 64-key-tile-contiguous: vf[bh*131072 + t64*2048 + ((ktk&3)*16 + ntb)*32 + ln]
        uint2* dst = vf + (size_t)bh * 131072;
        #pragma unroll
        for (int it = 0; it < 16; it++) {
            const int idx = tid + it * 256;
            const int blk = idx >> 5, ln = idx & 31;
            const int ktk = blk >> 4, ntb = blk & 15;
            const int g2 = ln >> 2, t2 = ln & 3;
            const int hd = ntb * 8 + g2, key0 = ktk * 16 + 2 * t2;
            const int t64 = nb * 2 + (ktk >> 2);
            uint2 o;
            o.x = pack_bf16x2(T[hd * 130 + key0],     T[hd * 130 + key0 + 1]);
            o.y = pack_bf16x2(T[hd * 130 + key0 + 8], T[hd * 130 + key0 + 9]);
            dst[(size_t)t64 * 2048 + ((ktk & 3) * 16 + ntb) * 32 + ln] = o;
        }
    }
}

// ---------------- proj GEMM: 4-stage pipeline, fp32 out + bias + residual ----------------
#define PROJ_SMEM 65536

__global__ void __launch_bounds__(256) gemm_bf16_kernel(const uint4* __restrict__ Af,
                                                        const uint2* __restrict__ Bf,
                                                        const float* __restrict__ bias,
                                                        const float* __restrict__ resid,
                                                        float* __restrict__ out, int M) {
    extern __shared__ char psm[];
    const uint32_t sb = smem_u32(psm);
    const int tid = threadIdx.x, w = tid >> 5, l = tid & 31;
    const int mi = w >> 1, nh = w & 1, gid = l >> 2, tig = l & 3;
    const int nb = blockIdx.x, mb = blockIdx.y, bz = blockIdx.z;
    Bf += (size_t)bz * 524288;
    out += (size_t)bz * M * L;
    if (resid) resid += (size_t)bz * M * L;

    auto issue = [&](int kc, int s) {
        #pragma unroll
        for (int j = 0; j < 2; j++) {
            const int e = tid + j * 256;
            const int bl = e >> 5, ln = e & 31;
            const int i = bl >> 1, ktl = bl & 1;
            cp16(sb + s * 16384 + e * 16,
                 (const char*)(Af + ((size_t)(mb * 8 + i) * 32 + kc * 2 + ktl) * 32 + ln));
        }
        #pragma unroll
        for (int j = 0; j < 2; j++) {
            const int f = tid + j * 256;
            const int bl = f >> 4, lp = f & 15;
            const int nt = bl >> 1, ktl = bl & 1;
            cp16(sb + s * 16384 + 8192 + bl * 256 + lp * 16,
                 (const char*)Bf + ((size_t)(nb * 16 + nt) * 32 + kc * 2 + ktl) * 256 + lp * 16);
        }
    };

    issue(0, 0); CP_COMMIT();
    issue(1, 1); CP_COMMIT();
    issue(2, 2); CP_COMMIT();
    float acc[2][8][4] = {};
    for (int t = 0; t < 16; t++) {
        if (t < 14)       { CP_WAIT(2); }
        else if (t == 14) { CP_WAIT(1); }
        else              { CP_WAIT(0); }
        __syncthreads();
        if (t + 3 < 16) { issue(t + 3, (t + 3) & 3); CP_COMMIT(); }
        const int s = t & 3;
        #pragma unroll
        for (int ktl = 0; ktl < 2; ktl++) {
            uint4 A0 = *(const uint4*)(psm + s * 16384 + (((mi * 2 + 0) * 2 + ktl) * 32 + l) * 16);
            uint4 A1 = *(const uint4*)(psm + s * 16384 + (((mi * 2 + 1) * 2 + ktl) * 32 + l) * 16);
            #pragma unroll
            for (int nt = 0; nt < 8; nt++) {
                uint2 B = *(const uint2*)(psm + s * 16384 + 8192 + (((nh * 8 + nt) * 2 + ktl) * 32 + l) * 8);
                MMA_BF16(acc[0][nt], A0, B);
                MMA_BF16(acc[1][nt], A1, B);
            }
        }
    }

    #pragma unroll
    for (int r = 0; r < 2; r++) {
        const int m0 = mb * 128 + mi * 32 + r * 16 + gid;
        const float b0v = bias[m0], b8v = bias[m0 + 8];
        #pragma unroll
        for (int nt = 0; nt < 8; nt++) {
            const int n0 = nb * 128 + nh * 64 + nt * 8 + 2 * tig;
            const size_t o0 = (size_t)m0 * L + n0, o8 = (size_t)(m0 + 8) * L + n0;
            float2 v0 = make_float2(acc[r][nt][0] + b0v, acc[r][nt][1] + b0v);
            float2 v8 = make_float2(acc[r][nt][2] + b8v, acc[r][nt][3] + b8v);
            if (resid) {
                float2 r0 = *(const float2*)(resid + o0);
                float2 r8 = *(const float2*)(resid + o8);
                v0.x += r0.x; v0.y += r0.y; v8.x += r8.x; v8.y += r8.y;
            }
            *(float2*)(out + o0) = v0;
            *(float2*)(out + o8) = v8;
        }
    }
}

// ---------------- attention: 64-key tiles, warp-private 16 queries, 2 CTAs/SM ----------------
// smem: Q 32KB | K 2x16KB | V 2x16KB = 96KB. Warp w owns queries [w*16, w*16+16).
#define SM_K 32768
#define SM_V 65536
#define ATT_SMEM 98304

__global__ void __launch_bounds__(256, 2) attn_bf16_kernel(const uint4* __restrict__ qf,
                                                           const uint2* __restrict__ kf,
                                                           const uint2* __restrict__ vf,
                                                           uint2* __restrict__ attf) {
    extern __shared__ char sm[];
    const uint32_t sb = smem_u32(sm);
    const int tid = threadIdx.x, w = tid >> 5, l = tid & 31;
    const int gid = l >> 2, tig = l & 3;
    const int qb = blockIdx.x, bh = blockIdx.y;
    const int b = bh >> 2, h = bh & 3;

    const char* qsrc = (const char*)(qf + ((size_t)bh * 32 + qb) * 2048);
    const char* ksrc = (const char*)(kf + (size_t)bh * 131072);
    const char* vsrc = (const char*)(vf + (size_t)bh * 131072);

    // prologue: Q 32KB + tile0 K/V 16KB each
    #pragma unroll
    for (int j = 0; j < 8; j++) {
        const int i = tid + j * 256;
        cp16(sb + i * 16, qsrc + i * 16);
    }
    #pragma unroll
    for (int j = 0; j < 4; j++) {
        const int i = tid + j * 256;
        cp16(sb + SM_K + i * 16, ksrc + i * 16);
        cp16(sb + SM_V + i * 16, vsrc + i * 16);
    }
    CP_COMMIT();

    float oacc[16][4] = {};
    float lsum[2] = {0.f, 0.f};

    for (int t = 0; t < 64; t++) {
        CP_WAIT(0);
        __syncthreads();
        if (t + 1 < 64) {
            const int pb = (t + 1) & 1;
            const char* kp = ksrc + (size_t)(t + 1) * 16384;
            const char* vp = vsrc + (size_t)(t + 1) * 16384;
            #pragma unroll
            for (int j = 0; j < 4; j++) {
                const int i = tid + j * 256;
                cp16(sb + SM_K + pb * 16384 + i * 16, kp + i * 16);
                cp16(sb + SM_V + pb * 16384 + i * 16, vp + i * 16);
            }
            CP_COMMIT();
        }

        const uint32_t Kb = SM_K + (t & 1) * 16384;
        const uint32_t Vb = SM_V + (t & 1) * 16384;

        // S = Q K^T : warp's 16 q x 64 keys
        float sacc[8][4] = {};
        #pragma unroll
        for (int ktc = 0; ktc < 8; ktc++) {
            uint4 A = *(const uint4*)(sm + ((w * 8 + ktc) * 32 + l) * 16);
            #pragma unroll
            for (int nt = 0; nt < 8; nt++) {
                uint2 B = *(const uint2*)(sm + Kb + ((ktc * 8 + nt) * 32 + l) * 8);
                MMA_BF16(sacc[nt], A, B);
            }
        }

        // exp + pack P per 16-key chunk, PV immediately (register P, no smem)
        #pragma unroll
        for (int kt = 0; kt < 4; kt++) {
            float p00 = __expf(sacc[2 * kt][0]),     p01 = __expf(sacc[2 * kt][1]);
            float p02 = __expf(sacc[2 * kt][2]),     p03 = __expf(sacc[2 * kt][3]);
            float p10 = __expf(sacc[2 * kt + 1][0]), p11 = __expf(sacc[2 * kt + 1][1]);
            float p12 = __expf(sacc[2 * kt + 1][2]), p13 = __expf(sacc[2 * kt + 1][3]);
            lsum[0] += p00 + p01 + p10 + p11;
            lsum[1] += p02 + p03 + p12 + p13;
            uint4 A;
            A.x = pack_bf16x2(p00, p01);
            A.y = pack_bf16x2(p02, p03);
            A.z = pack_bf16x2(p10, p11);
            A.w = pack_bf16x2(p12, p13);
            #pragma unroll
            for (int nt = 0; nt < 16; nt++) {
                uint2 B = *(const uint2*)(sm + Vb + ((kt * 16 + nt) * 32 + l) * 8);
                MMA_BF16(oacc[nt], A, B);
            }
        }
    }

    // lsum full per-row sums: quad reduce (keys split over tig only)
    #pragma unroll
    for (int r = 0; r < 2; r++) {
        float v = lsum[r];
        v += __shfl_xor_sync(0xffffffffu, v, 1);
        v += __shfl_xor_sync(0xffffffffu, v, 2);
        lsum[r] = v;
    }
    __syncthreads();   // all K/V/Q smem reads done; reuse for warp-private Ob

    float* Obw = (float*)sm + w * 2112;   // [16 q][stride 132] fp32
    const float linv0 = 1.0f / lsum[0], linv1 = 1.0f / lsum[1];
    #pragma unroll
    for (int nt = 0; nt < 16; nt++) {
        #pragma unroll
        for (int j = 0; j < 4; j++) {
            const int qg = gid + 8 * (j >> 1);
            const int hd = nt * 8 + 2 * tig + (j & 1);
            Obw[qg * 132 + hd] = oacc[nt][j] * ((j >> 1) ? linv1 : linv0);
        }
    }
    __syncwarp();

    // pack proj B-frags (warp-private: 2 ntl x 8 ktl blocks)
    const size_t attbase = (size_t)b * 524288;
    #pragma unroll
    for (int bi = 0; bi < 16; bi++) {
        const int ntl = bi >> 3, ktl = bi & 7;
        const int g2 = l >> 2, t2 = l & 3;
        const int qg = ntl * 8 + g2;
        const int c = ktl * 16 + 2 * t2;
        uint2 o;
        o.x = pack_bf16x2(Obw[qg * 132 + c],     Obw[qg * 132 + c + 1]);
        o.y = pack_bf16x2(Obw[qg * 132 + c + 8], Obw[qg * 132 + c + 9]);
        const int ntg = qb * 16 + w * 2 + ntl;
        attf[attbase + ((size_t)ntg * 32 + h * 8 + ktl) * 32 + l] = o;
    }
}

// ---------------- host ----------------
extern "C" void kernel_launch(void* const* d_in, const int* in_sizes, int n_in,
                              void* d_out, int out_size) {
    const float* x      = (const float*)d_in[0];
    const float* gn_w   = (const float*)d_in[1];
    const float* gn_b   = (const float*)d_in[2];
    const float* w_qkv  = (const float*)d_in[3];
    const float* b_qkv  = (const float*)d_in[4];
    const float* w_proj = (const float*)d_in[5];
    const float* b_proj = (const float*)d_in[6];
    float* out = (float*)d_out;

    uint4 *qf_p, *wqf_p, *wpf_p;
    uint2 *kf_p, *vf_p, *xnf_p, *attf_p;
    cudaGetSymbolAddress((void**)&qf_p, g_qf);
    cudaGetSymbolAddress((void**)&kf_p, g_kf);
    cudaGetSymbolAddress((void**)&vf_p, g_vf);
    cudaGetSymbolAddress((void**)&xnf_p, g_xnf);
    cudaGetSymbolAddress((void**)&attf_p, g_attf);
    cudaGetSymbolAddress((void**)&wqf_p, g_wqf);
    cudaGetSymbolAddress((void**)&wpf_p, g_wpf);

    // 1) GroupNorm fused with xn fragment packing; weight packing
    groupnorm_pack_kernel<<<dim3(GROUPS, BATCH), 256>>>(x, gn_w, gn_b, xnf_p);
    pack_w_kernel<<<384, 256>>>(w_qkv, wqf_p);
    pack_w_kernel<<<128, 256>>>(w_proj, wpf_p);

    // 2) QKV GEMM (4-stage) with fused q/k/v fragment epilogue
    cudaFuncSetAttribute(gemm_qkv_kernel, cudaFuncAttributeMaxDynamicSharedMemorySize, QKV_SMEM);
    gemm_qkv_kernel<<<dim3(32, 12, BATCH), 256, QKV_SMEM>>>(wqf_p, xnf_p, b_qkv,
                                                            qf_p, kf_p, vf_p);

    // 3) attention (64-key tiles, 2 CTAs/SM), emits proj B-frags
    cudaFuncSetAttribute(attn_bf16_kernel, cudaFuncAttributeMaxDynamicSharedMemorySize, ATT_SMEM);
    attn_bf16_kernel<<<dim3(L / 128, BATCH * NH), 256, ATT_SMEM>>>(qf_p, kf_p, vf_p, attf_p);

    // 4) proj GEMM (4-stage) + bias + residual -> out
    cudaFuncSetAttribute(gemm_bf16_kernel, cudaFuncAttributeMaxDynamicSharedMemorySize, PROJ_SMEM);
    gemm_bf16_kernel<<<dim3(32, 4, BATCH), 256, PROJ_SMEM>>>(wpf_p, attf_p, b_proj, x, out, C);
}

// round 9
// speedup vs baseline: 1.0088x; 1.0088x over previous
#include <cuda_runtime.h>
#include <math.h>
#include <stdint.h>

#define BATCH 2
#define C 512
#define L 4096
#define NH 4
#define HD 128
#define GROUPS 32
#define CPG (C / GROUPS)   // 16
#define EPS 1e-5f

// ---------------- scratch (static device globals; no allocation) ----------------
__device__ uint4 g_qf[(size_t)BATCH * NH * 32 * 2048];   // 8 MB  Q A-frags (k16 per uint4)
__device__ uint4 g_kf[(size_t)BATCH * NH * 32 * 2048];   // 8 MB  K B-frags (k32 per uint4)
__device__ uint4 g_vf[(size_t)BATCH * NH * 32 * 2048];   // 8 MB  V B-frags (k32 per uint4)
__device__ uint4 g_xnf[(size_t)BATCH * 262144];          // 8 MB  xn B-frags (k32 per uint4)
__device__ uint4 g_attf[(size_t)BATCH * 262144];         // 8 MB  att B-frags (k32 per uint4)
__device__ uint4 g_wqf[(size_t)96 * 32 * 32];            // 1.5MB w_qkv A-frags
__device__ uint4 g_wpf[(size_t)32 * 32 * 32];            // 0.5MB w_proj A-frags

__device__ __forceinline__ uint32_t smem_u32(const void* p) {
    uint32_t a;
    asm("{ .reg .u64 t; cvta.to.shared.u64 t, %1; cvt.u32.u64 %0, t; }" : "=r"(a) : "l"(p));
    return a;
}
__device__ __forceinline__ uint32_t pack_bf16x2(float lo, float hi) {
    uint32_t d;
    asm("cvt.rn.bf16x2.f32 %0, %1, %2;" : "=r"(d) : "f"(hi), "f"(lo));
    return d;
}
__device__ __forceinline__ float ex2f(float x) {
    float r; asm("ex2.approx.ftz.f32 %0, %1;" : "=f"(r) : "f"(x)); return r;
}
#define MMA_BF16(d, a, b) \
    asm volatile("mma.sync.aligned.m16n8k16.row.col.f32.bf16.bf16.f32 " \
                 "{%0,%1,%2,%3}, {%4,%5,%6,%7}, {%8,%9}, {%0,%1,%2,%3};" \
                 : "+f"((d)[0]), "+f"((d)[1]), "+f"((d)[2]), "+f"((d)[3]) \
                 : "r"((a).x), "r"((a).y), "r"((a).z), "r"((a).w), \
                   "r"((b).x), "r"((b).y))

__device__ __forceinline__ void cp16(uint32_t dst, const void* src) {
    asm volatile("cp.async.cg.shared.global [%0], [%1], 16;" :: "r"(dst), "l"(src));
}
#define CP_COMMIT() asm volatile("cp.async.commit_group;" ::: "memory")
#define CP_WAIT(n)  asm volatile("cp.async.wait_group %0;" :: "n"(n) : "memory")

// ---------------- GroupNorm fused with xn B-frag (k32 uint4) packing ----------------
// group g covers channels [16g,16g+16) = half of k32 chunk kc=g>>1 (half = g&1).
__global__ void __launch_bounds__(256) groupnorm_pack_kernel(const float* __restrict__ x,
                                                             const float* __restrict__ gw,
                                                             const float* __restrict__ gb,
                                                             uint2* __restrict__ Bf2) {
    const int g = blockIdx.x, b = blockIdx.y;
    const int tid = threadIdx.x;
    const size_t base = ((size_t)b * C + g * CPG) * L;
    const int SPAN = CPG * L;
    const float* xr = x + base;
    const float4* x4 = (const float4*)xr;
    float s = 0.f, ss = 0.f;
    for (int i = tid; i < SPAN / 4; i += 256) {
        float4 v = x4[i];
        s  += v.x + v.y + v.z + v.w;
        ss += v.x * v.x + v.y * v.y + v.z * v.z + v.w * v.w;
    }
    __shared__ float rs[256], rss[256];
    rs[tid] = s; rss[tid] = ss;
    __syncthreads();
    for (int off = 128; off; off >>= 1) {
        if (tid < off) { rs[tid] += rs[tid + off]; rss[tid] += rss[tid + off]; }
        __syncthreads();
    }
    __shared__ float ga_s[CPG], be_s[CPG];
    if (tid < CPG) {
        float mean = rs[0] / SPAN;
        float var  = rss[0] / SPAN - mean * mean;
        float rstd = rsqrtf(var + EPS);
        float ga = gw[g * CPG + tid] * rstd;
        ga_s[tid] = ga;
        be_s[tid] = gb[g * CPG + tid] - mean * ga;
    }
    __syncthreads();

    // uint2 half-writes into uint4 layout Bf4[b][(nt*16 + kc)*32 + lane]
    const int kc = g >> 1, half = g & 1;
    uint2* dst = Bf2 + ((size_t)b * 262144 + (size_t)kc * 32) * 2 + half;
    for (int i = tid; i < 16384; i += 256) {
        const int nt = i >> 5, lane = i & 31;
        const int gid = lane >> 2, tig = lane & 3;
        const int n = nt * 8 + gid;
        const int lc = 2 * tig;
        float v0 = xr[(size_t)lc * L + n]       * ga_s[lc]     + be_s[lc];
        float v1 = xr[(size_t)(lc + 1) * L + n] * ga_s[lc + 1] + be_s[lc + 1];
        float v8 = xr[(size_t)(lc + 8) * L + n] * ga_s[lc + 8] + be_s[lc + 8];
        float v9 = xr[(size_t)(lc + 9) * L + n] * ga_s[lc + 9] + be_s[lc + 9];
        uint2 o;
        o.x = pack_bf16x2(v0, v1);
        o.y = pack_bf16x2(v8, v9);
        dst[((size_t)nt * 16 * 32 + lane) * 2] = o;
    }
}

// ---------------- weight packing (A-frags, k16 per uint4) ----------------
__global__ void __launch_bounds__(256) pack_w_kernel(const float* __restrict__ W,
                                                     uint4* __restrict__ Wf) {
    const int idx = blockIdx.x * 256 + threadIdx.x;
    const int blk = idx >> 5, lane = idx & 31;
    const int mt = blk >> 5, kt = blk & 31;
    const int gid = lane >> 2, tig = lane & 3;
    const float* r0 = W + (size_t)(mt * 16 + gid) * 512 + kt * 16;
    const float* r8 = r0 + 8 * 512;
    float2 a0 = *(const float2*)(r0 + 2 * tig);
    float2 a1 = *(const float2*)(r8 + 2 * tig);
    float2 a2 = *(const float2*)(r0 + 2 * tig + 8);
    float2 a3 = *(const float2*)(r8 + 2 * tig + 8);
    uint4 o;
    o.x = pack_bf16x2(a0.x, a0.y); o.y = pack_bf16x2(a1.x, a1.y);
    o.z = pack_bf16x2(a2.x, a2.y); o.w = pack_bf16x2(a3.x, a3.y);
    Wf[idx] = o;
}

// ---------------- QKV GEMM: 4-stage pipeline + fused q/k/v fragment epilogue ----------------
#define QKV_SMEM 66560   // max(4 x 16KB staging, 128x130 fp32 T)

__global__ void __launch_bounds__(256) gemm_qkv_kernel(const uint4* __restrict__ Af,
                                                       const uint4* __restrict__ Bf4,
                                                       const float* __restrict__ bias,
                                                       uint4* __restrict__ qf,
                                                       uint4* __restrict__ kf,
                                                       uint4* __restrict__ vf) {
    extern __shared__ char dynsm[];
    const uint32_t sb = smem_u32(dynsm);
    float* T = (float*)dynsm;
    const int tid = threadIdx.x, w = tid >> 5, l = tid & 31;
    const int mi = w >> 1, nh = w & 1, gid = l >> 2, tig = l & 3;
    const int nb = blockIdx.x, mb = blockIdx.y, bz = blockIdx.z;
    Bf4 += (size_t)bz * 262144;

    auto issue = [&](int kc, int s) {
        #pragma unroll
        for (int j = 0; j < 2; j++) {          // A: 512 x 16B (k16 frags)
            const int e = tid + j * 256;
            const int bl = e >> 5, ln = e & 31;
            const int i = bl >> 1, ktl = bl & 1;
            cp16(sb + s * 16384 + e * 16,
                 (const char*)(Af + ((size_t)(mb * 8 + i) * 32 + kc * 2 + ktl) * 32 + ln));
        }
        #pragma unroll
        for (int j = 0; j < 2; j++) {          // B: 512 x 16B (k32 frags)
            const int f = tid + j * 256;
            const int nt = f >> 5, ln = f & 31;
            cp16(sb + s * 16384 + 8192 + f * 16,
                 (const char*)(Bf4 + ((size_t)(nb * 16 + nt) * 16 + kc) * 32 + ln));
        }
    };

    issue(0, 0); CP_COMMIT();
    issue(1, 1); CP_COMMIT();
    issue(2, 2); CP_COMMIT();
    float acc[2][8][4] = {};
    for (int t = 0; t < 16; t++) {
        if (t < 14)       { CP_WAIT(2); }
        else if (t == 14) { CP_WAIT(1); }
        else              { CP_WAIT(0); }
        __syncthreads();
        if (t + 3 < 16) { issue(t + 3, (t + 3) & 3); CP_COMMIT(); }
        const int s = t & 3;
        uint4 A00 = *(const uint4*)(dynsm + s * 16384 + (((mi * 2 + 0) * 2 + 0) * 32 + l) * 16);
        uint4 A01 = *(const uint4*)(dynsm + s * 16384 + (((mi * 2 + 0) * 2 + 1) * 32 + l) * 16);
        uint4 A10 = *(const uint4*)(dynsm + s * 16384 + (((mi * 2 + 1) * 2 + 0) * 32 + l) * 16);
        uint4 A11 = *(const uint4*)(dynsm + s * 16384 + (((mi * 2 + 1) * 2 + 1) * 32 + l) * 16);
        #pragma unroll
        for (int nt = 0; nt < 8; nt++) {
            uint4 Bp = *(const uint4*)(dynsm + s * 16384 + 8192 + (((nh * 8 + nt)) * 32 + l) * 16);
            uint2 b0; b0.x = Bp.x; b0.y = Bp.y;
            uint2 b1; b1.x = Bp.z; b1.y = Bp.w;
            MMA_BF16(acc[0][nt], A00, b0);
            MMA_BF16(acc[0][nt], A01, b1);
            MMA_BF16(acc[1][nt], A10, b0);
            MMA_BF16(acc[1][nt], A11, b1);
        }
    }
    __syncthreads();   // staging dead before T overwrites it

    const int sec = mb >> 2, h = mb & 3;
    const int bh = bz * NH + h;
    // Q scale folds 1/sqrt(128) * log2(e) so attention can use raw ex2
    const float qs = (sec == 0) ? (0.08838834764831845f * 1.4426950408889634f) : 1.0f;

    #pragma unroll
    for (int r = 0; r < 2; r++) {
        const int m0 = mi * 32 + r * 16 + gid;
        const float b0v = bias[mb * 128 + m0], b8v = bias[mb * 128 + m0 + 8];
        #pragma unroll
        for (int nt = 0; nt < 8; nt++) {
            const int n0 = nh * 64 + nt * 8 + 2 * tig;
            T[m0 * 130 + n0]           = (acc[r][nt][0] + b0v) * qs;
            T[m0 * 130 + n0 + 1]       = (acc[r][nt][1] + b0v) * qs;
            T[(m0 + 8) * 130 + n0]     = (acc[r][nt][2] + b8v) * qs;
            T[(m0 + 8) * 130 + n0 + 1] = (acc[r][nt][3] + b8v) * qs;
        }
    }
    __syncthreads();

    if (sec == 0) {
        // Q A-frags (k16): qf[(bh*32 + nb)*2048 + (mtb*8 + ktc)*32 + ln]
        uint4* dst = qf + ((size_t)bh * 32 + nb) * 2048;
        #pragma unroll
        for (int it = 0; it < 8; it++) {
            const int idx = tid + it * 256;
            const int blk = idx >> 5, ln = idx & 31;
            const int mtb = blk >> 3, ktc = blk & 7;
            const int g2 = ln >> 2, t2 = ln & 3;
            const int q = mtb * 16 + g2, c = ktc * 16 + 2 * t2;
            uint4 o;
            o.x = pack_bf16x2(T[c * 130 + q],           T[(c + 1) * 130 + q]);
            o.y = pack_bf16x2(T[c * 130 + q + 8],       T[(c + 1) * 130 + q + 8]);
            o.z = pack_bf16x2(T[(c + 8) * 130 + q],     T[(c + 9) * 130 + q]);
            o.w = pack_bf16x2(T[(c + 8) * 130 + q + 8], T[(c + 9) * 130 + q + 8]);
            dst[idx] = o;
        }
    } else if (sec == 1) {
        // K B-frags (k32): kf[(bh*32 + nb)*2048 + (kc32*16 + ntb)*32 + ln]
        uint4* dst = kf + ((size_t)bh * 32 + nb) * 2048;
        #pragma unroll
        for (int it = 0; it < 8; it++) {
            const int idx = tid + it * 256;
            const int blk = idx >> 5, ln = idx & 31;
            const int kc32 = blk >> 4, ntb = blk & 15;
            const int g2 = ln >> 2, t2 = ln & 3;
            const int key = ntb * 8 + g2, c0 = kc32 * 32 + 2 * t2;
            uint4 o;
            o.x = pack_bf16x2(T[c0 * 130 + key],        T[(c0 + 1) * 130 + key]);
            o.y = pack_bf16x2(T[(c0 + 8) * 130 + key],  T[(c0 + 9) * 130 + key]);
            o.z = pack_bf16x2(T[(c0 + 16) * 130 + key], T[(c0 + 17) * 130 + key]);
            o.w = pack_bf16x2(T[(c0 + 24) * 130 + key], T[(c0 + 25) * 130 + key]);
            dst[idx] = o;
        }
    } else {
        // V B-frags (k32 over keys): vf[(bh*32 + nb)*2048 + (kk32*16 + ntb)*32 + ln]
        uint4* dst = vf + ((size_t)bh * 32 + nb) * 2048;
        #pragma unroll
        for (int it = 0; it < 8; it++) {
            const int idx = tid + it * 256;
            const int blk = idx >> 5, ln = idx & 31;
            const int kk32 = blk >> 4, ntb = blk & 15;
            const int g2 = ln >> 2, t2 = ln & 3;
            const int hd = ntb * 8 + g2, k0 = kk32 * 32 + 2 * t2;
            uint4 o;
            o.x = pack_bf16x2(T[hd * 130 + k0],      T[hd * 130 + k0 + 1]);
            o.y = pack_bf16x2(T[hd * 130 + k0 + 8],  T[hd * 130 + k0 + 9]);
            o.z = pack_bf16x2(T[hd * 130 + k0 + 16], T[hd * 130 + k0 + 17]);
            o.w = pack_bf16x2(T[hd * 130 + k0 + 24], T[hd * 130 + k0 + 25]);
            dst[idx] = o;
        }
    }
}

// ---------------- proj GEMM: 4-stage pipeline, fp32 out + bias + residual ----------------
#define PROJ_SMEM 65536

__global__ void __launch_bounds__(256) gemm_bf16_kernel(const uint4* __restrict__ Af,
                                                        const uint4* __restrict__ Bf4,
                                                        const float* __restrict__ bias,
                                                        const float* __restrict__ resid,
                                                        float* __restrict__ out, int M) {
    extern __shared__ char psm[];
    const uint32_t sb = smem_u32(psm);
    const int tid = threadIdx.x, w = tid >> 5, l = tid & 31;
    const int mi = w >> 1, nh = w & 1, gid = l >> 2, tig = l & 3;
    const int nb = blockIdx.x, mb = blockIdx.y, bz = blockIdx.z;
    Bf4 += (size_t)bz * 262144;
    out += (size_t)bz * M * L;
    if (resid) resid += (size_t)bz * M * L;

    auto issue = [&](int kc, int s) {
        #pragma unroll
        for (int j = 0; j < 2; j++) {
            const int e = tid + j * 256;
            const int bl = e >> 5, ln = e & 31;
            const int i = bl >> 1, ktl = bl & 1;
            cp16(sb + s * 16384 + e * 16,
                 (const char*)(Af + ((size_t)(mb * 8 + i) * 32 + kc * 2 + ktl) * 32 + ln));
        }
        #pragma unroll
        for (int j = 0; j < 2; j++) {
            const int f = tid + j * 256;
            const int nt = f >> 5, ln = f & 31;
            cp16(sb + s * 16384 + 8192 + f * 16,
                 (const char*)(Bf4 + ((size_t)(nb * 16 + nt) * 16 + kc) * 32 + ln));
        }
    };

    issue(0, 0); CP_COMMIT();
    issue(1, 1); CP_COMMIT();
    issue(2, 2); CP_COMMIT();
    float acc[2][8][4] = {};
    for (int t = 0; t < 16; t++) {
        if (t < 14)       { CP_WAIT(2); }
        else if (t == 14) { CP_WAIT(1); }
        else              { CP_WAIT(0); }
        __syncthreads();
        if (t + 3 < 16) { issue(t + 3, (t + 3) & 3); CP_COMMIT(); }
        const int s = t & 3;
        uint4 A00 = *(const uint4*)(psm + s * 16384 + (((mi * 2 + 0) * 2 + 0) * 32 + l) * 16);
        uint4 A01 = *(const uint4*)(psm + s * 16384 + (((mi * 2 + 0) * 2 + 1) * 32 + l) * 16);
        uint4 A10 = *(const uint4*)(psm + s * 16384 + (((mi * 2 + 1) * 2 + 0) * 32 + l) * 16);
        uint4 A11 = *(const uint4*)(psm + s * 16384 + (((mi * 2 + 1) * 2 + 1) * 32 + l) * 16);
        #pragma unroll
        for (int nt = 0; nt < 8; nt++) {
            uint4 Bp = *(const uint4*)(psm + s * 16384 + 8192 + (((nh * 8 + nt)) * 32 + l) * 16);
            uint2 b0; b0.x = Bp.x; b0.y = Bp.y;
            uint2 b1; b1.x = Bp.z; b1.y = Bp.w;
            MMA_BF16(acc[0][nt], A00, b0);
            MMA_BF16(acc[0][nt], A01, b1);
            MMA_BF16(acc[1][nt], A10, b0);
            MMA_BF16(acc[1][nt], A11, b1);
        }
    }

    #pragma unroll
    for (int r = 0; r < 2; r++) {
        const int m0 = mb * 128 + mi * 32 + r * 16 + gid;
        const float b0v = bias[m0], b8v = bias[m0 + 8];
        #pragma unroll
        for (int nt = 0; nt < 8; nt++) {
            const int n0 = nb * 128 + nh * 64 + nt * 8 + 2 * tig;
            const size_t o0 = (size_t)m0 * L + n0, o8 = (size_t)(m0 + 8) * L + n0;
            float2 v0 = make_float2(acc[r][nt][0] + b0v, acc[r][nt][1] + b0v);
            float2 v8 = make_float2(acc[r][nt][2] + b8v, acc[r][nt][3] + b8v);
            if (resid) {
                float2 r0 = *(const float2*)(resid + o0);
                float2 r8 = *(const float2*)(resid + o8);
                v0.x += r0.x; v0.y += r0.y; v8.x += r8.x; v8.y += r8.y;
            }
            *(float2*)(out + o0) = v0;
            *(float2*)(out + o8) = v8;
        }
    }
}

// ---------------- attention (R7 structure, k32 B-frags, ex2 softmax) ----------------
// Warp (qi, kh): 32 queries, key half kh (64 keys) -> partial O over full 128 hd.
// smem: Q 32K | K 2x32K | V 2x32K = 160KB; Ob overlays Q/K at the end.
#define SM_K0 32768
#define SM_V0 98304
#define ATT_SMEM 163840

__global__ void __launch_bounds__(256) attn_bf16_kernel(const uint4* __restrict__ qf,
                                                        const uint4* __restrict__ kf,
                                                        const uint4* __restrict__ vf,
                                                        uint4* __restrict__ attf) {
    extern __shared__ char sm[];
    const uint32_t sb = smem_u32(sm);
    __shared__ float lsum_s[2][128];

    const int tid = threadIdx.x, w = tid >> 5, l = tid & 31;
    const int qi = w >> 1, kh = w & 1;
    const int gid = l >> 2, tig = l & 3;
    const int qb = blockIdx.x, bh = blockIdx.y;
    const int b = bh >> 2, h = bh & 3;

    const char* qsrc = (const char*)(qf + ((size_t)bh * 32 + qb) * 2048);
    const char* ksrc = (const char*)(kf + (size_t)bh * 32 * 2048);
    const char* vsrc = (const char*)(vf + (size_t)bh * 32 * 2048);

    #pragma unroll
    for (int j = 0; j < 8; j++) {
        const int i = tid + j * 256;
        cp16(sb + i * 16, qsrc + i * 16);
        cp16(sb + SM_K0 + i * 16, ksrc + i * 16);
        cp16(sb + SM_V0 + i * 16, vsrc + i * 16);
    }
    CP_COMMIT();

    float oacc[2][16][4] = {};
    float lsum[2][2] = {};

    for (int t = 0; t < 32; t++) {
        CP_WAIT(0);
        __syncthreads();
        if (t + 1 < 32) {
            const int pb = (t + 1) & 1;
            const char* kp = ksrc + (size_t)(t + 1) * 32768;
            const char* vp = vsrc + (size_t)(t + 1) * 32768;
            #pragma unroll
            for (int j = 0; j < 8; j++) {
                const int i = tid + j * 256;
                cp16(sb + SM_K0 + pb * 32768 + i * 16, kp + i * 16);
                cp16(sb + SM_V0 + pb * 32768 + i * 16, vp + i * 16);
            }
            CP_COMMIT();
        }

        const uint32_t Kb = SM_K0 + (t & 1) * 32768;
        // ---- S = Q K^T (warp: 32q x its 64-key half) ----
        float sacc[2][8][4] = {};
        #pragma unroll
        for (int kc = 0; kc < 4; kc++) {
            uint4 A00 = *(const uint4*)(sm + (((qi * 2 + 0) * 8 + 2 * kc) * 32 + l) * 16);
            uint4 A01 = *(const uint4*)(sm + (((qi * 2 + 0) * 8 + 2 * kc + 1) * 32 + l) * 16);
            uint4 A10 = *(const uint4*)(sm + (((qi * 2 + 1) * 8 + 2 * kc) * 32 + l) * 16);
            uint4 A11 = *(const uint4*)(sm + (((qi * 2 + 1) * 8 + 2 * kc + 1) * 32 + l) * 16);
            #pragma unroll
            for (int nt = 0; nt < 8; nt++) {
                uint4 Bp = *(const uint4*)(sm + Kb + ((kc * 16 + kh * 8 + nt) * 32 + l) * 16);
                uint2 b0; b0.x = Bp.x; b0.y = Bp.y;
                uint2 b1; b1.x = Bp.z; b1.y = Bp.w;
                MMA_BF16(sacc[0][nt], A00, b0);
                MMA_BF16(sacc[0][nt], A01, b1);
                MMA_BF16(sacc[1][nt], A10, b0);
                MMA_BF16(sacc[1][nt], A11, b1);
            }
        }

        // ---- ex2 (scale pre-folded with log2e) + pack P into A-frag registers ----
        uint4 pP[2][4];
        #pragma unroll
        for (int mt = 0; mt < 2; mt++) {
            #pragma unroll
            for (int kc = 0; kc < 4; kc++) {
                const int nt0 = 2 * kc, nt1 = 2 * kc + 1;
                float p00 = ex2f(sacc[mt][nt0][0]), p01 = ex2f(sacc[mt][nt0][1]);
                float p02 = ex2f(sacc[mt][nt0][2]), p03 = ex2f(sacc[mt][nt0][3]);
                float p10 = ex2f(sacc[mt][nt1][0]), p11 = ex2f(sacc[mt][nt1][1]);
                float p12 = ex2f(sacc[mt][nt1][2]), p13 = ex2f(sacc[mt][nt1][3]);
                lsum[mt][0] += p00 + p01 + p10 + p11;
                lsum[mt][1] += p02 + p03 + p12 + p13;
                pP[mt][kc].x = pack_bf16x2(p00, p01);
                pP[mt][kc].y = pack_bf16x2(p02, p03);
                pP[mt][kc].z = pack_bf16x2(p10, p11);
                pP[mt][kc].w = pack_bf16x2(p12, p13);
            }
        }

        // ---- O += P V over this warp's 64 keys, all 128 hd ----
        const uint32_t Vb = SM_V0 + (t & 1) * 32768;
        #pragma unroll
        for (int kk = 0; kk < 2; kk++) {
            const uint4 A0a = pP[0][2 * kk], A0b = pP[0][2 * kk + 1];
            const uint4 A1a = pP[1][2 * kk], A1b = pP[1][2 * kk + 1];
            #pragma unroll
            for (int nt = 0; nt < 16; nt++) {
                uint4 Bp = *(const uint4*)(sm + Vb + (((kh * 2 + kk) * 16 + nt) * 32 + l) * 16);
                uint2 b0; b0.x = Bp.x; b0.y = Bp.y;
                uint2 b1; b1.x = Bp.z; b1.y = Bp.w;
                MMA_BF16(oacc[0][nt], A0a, b0);
                MMA_BF16(oacc[0][nt], A0b, b1);
                MMA_BF16(oacc[1][nt], A1a, b0);
                MMA_BF16(oacc[1][nt], A1b, b1);
            }
        }
    }

    // ---- lsum quad-reduce, publish per key-half ----
    #pragma unroll
    for (int mt = 0; mt < 2; mt++)
        #pragma unroll
        for (int dr = 0; dr < 2; dr++) {
            float v = lsum[mt][dr];
            v += __shfl_xor_sync(0xffffffffu, v, 1);
            v += __shfl_xor_sync(0xffffffffu, v, 2);
            lsum[mt][dr] = v;
        }
    __syncthreads();   // all compute done; smem free for Ob
    float* Ob = (float*)sm;   // [128 hd][stride 132] fp32
    if (tig == 0) {
        #pragma unroll
        for (int mt = 0; mt < 2; mt++)
            #pragma unroll
            for (int dr = 0; dr < 2; dr++)
                lsum_s[kh][qi * 32 + mt * 16 + gid + 8 * dr] = lsum[mt][dr];
    }
    if (kh == 0) {
        #pragma unroll
        for (int mt = 0; mt < 2; mt++)
            #pragma unroll
            for (int nt = 0; nt < 16; nt++)
                #pragma unroll
                for (int j = 0; j < 4; j++) {
                    const int q  = qi * 32 + mt * 16 + gid + 8 * (j >> 1);
                    const int hd = nt * 8 + tig * 2 + (j & 1);
                    Ob[hd * 132 + q] = oacc[mt][nt][j];
                }
    }
    __syncthreads();
    if (kh == 1) {
        #pragma unroll
        for (int mt = 0; mt < 2; mt++)
            #pragma unroll
            for (int nt = 0; nt < 16; nt++)
                #pragma unroll
                for (int j = 0; j < 4; j++) {
                    const int q  = qi * 32 + mt * 16 + gid + 8 * (j >> 1);
                    const int hd = nt * 8 + tig * 2 + (j & 1);
                    Ob[hd * 132 + q] += oacc[mt][nt][j];
                }
    }
    __syncthreads();

    // ---- pack proj B-frags (k32 uint4) with normalization ----
    const size_t attbase = (size_t)b * 262144;
    #pragma unroll
    for (int it = 0; it < 8; it++) {
        const int slot = tid + it * 256;
        const int lb = slot >> 5, ln = slot & 31;
        const int ntl = lb >> 2, kc = lb & 3;
        const int g2 = ln >> 2, t2 = ln & 3;
        const int cl = kc * 32 + 2 * t2;
        const int ql = ntl * 8 + g2;
        const float linv = 1.0f / (lsum_s[0][ql] + lsum_s[1][ql]);
        uint4 o;
        o.x = pack_bf16x2(Ob[cl * 132 + ql] * linv,        Ob[(cl + 1) * 132 + ql] * linv);
        o.y = pack_bf16x2(Ob[(cl + 8) * 132 + ql] * linv,  Ob[(cl + 9) * 132 + ql] * linv);
        o.z = pack_bf16x2(Ob[(cl + 16) * 132 + ql] * linv, Ob[(cl + 17) * 132 + ql] * linv);
        o.w = pack_bf16x2(Ob[(cl + 24) * 132 + ql] * linv, Ob[(cl + 25) * 132 + ql] * linv);
        attf[attbase + ((size_t)(qb * 16 + ntl) * 16 + h * 4 + kc) * 32 + ln] = o;
    }
}

// ---------------- host ----------------
extern "C" void kernel_launch(void* const* d_in, const int* in_sizes, int n_in,
                              void* d_out, int out_size) {
    const float* x      = (const float*)d_in[0];
    const float* gn_w   = (const float*)d_in[1];
    const float* gn_b   = (const float*)d_in[2];
    const float* w_qkv  = (const float*)d_in[3];
    const float* b_qkv  = (const float*)d_in[4];
    const float* w_proj = (const float*)d_in[5];
    const float* b_proj = (const float*)d_in[6];
    float* out = (float*)d_out;

    uint4 *qf_p, *kf_p, *vf_p, *xnf_p, *attf_p, *wqf_p, *wpf_p;
    cudaGetSymbolAddress((void**)&qf_p, g_qf);
    cudaGetSymbolAddress((void**)&kf_p, g_kf);
    cudaGetSymbolAddress((void**)&vf_p, g_vf);
    cudaGetSymbolAddress((void**)&xnf_p, g_xnf);
    cudaGetSymbolAddress((void**)&attf_p, g_attf);
    cudaGetSymbolAddress((void**)&wqf_p, g_wqf);
    cudaGetSymbolAddress((void**)&wpf_p, g_wpf);

    // 1) GroupNorm fused with xn fragment packing; weight packing
    groupnorm_pack_kernel<<<dim3(GROUPS, BATCH), 256>>>(x, gn_w, gn_b, (uint2*)xnf_p);
    pack_w_kernel<<<384, 256>>>(w_qkv, wqf_p);
    pack_w_kernel<<<128, 256>>>(w_proj, wpf_p);

    // 2) QKV GEMM (4-stage) with fused q/k/v fragment epilogue
    cudaFuncSetAttribute(gemm_qkv_kernel, cudaFuncAttributeMaxDynamicSharedMemorySize, QKV_SMEM);
    gemm_qkv_kernel<<<dim3(32, 12, BATCH), 256, QKV_SMEM>>>(wqf_p, xnf_p, b_qkv,
                                                            qf_p, kf_p, vf_p);

    // 3) attention (128-key tiles, register P, k32 B-frags), emits proj B-frags
    cudaFuncSetAttribute(attn_bf16_kernel, cudaFuncAttributeMaxDynamicSharedMemorySize, ATT_SMEM);
    attn_bf16_kernel<<<dim3(L / 128, BATCH * NH), 256, ATT_SMEM>>>(qf_p, kf_p, vf_p, attf_p);

    // 4) proj GEMM (4-stage) + bias + residual -> out
    cudaFuncSetAttribute(gemm_bf16_kernel, cudaFuncAttributeMaxDynamicSharedMemorySize, PROJ_SMEM);
    gemm_bf16_kernel<<<dim3(32, 4, BATCH), 256, PROJ_SMEM>>>(wpf_p, attf_p, b_proj, x, out, C);
}

// round 10
// speedup vs baseline: 1.0594x; 1.0502x over previous
#include <cuda_runtime.h>
#include <math.h>
#include <stdint.h>

#define BATCH 2
#define C 512
#define L 4096
#define NH 4
#define HD 128
#define GROUPS 32
#define CPG (C / GROUPS)   // 16
#define EPS 1e-5f

// ---------------- scratch (static device globals; no allocation) ----------------
__device__ uint4 g_qf[(size_t)BATCH * NH * 32 * 2048];   // 8 MB  Q A-frags
__device__ uint2 g_kf[(size_t)BATCH * NH * 32 * 4096];   // 8 MB  K B-frags
__device__ uint2 g_vf[(size_t)BATCH * NH * 32 * 4096];   // 8 MB  V B-frags
__device__ uint2 g_xnf[(size_t)BATCH * 512 * 32 * 32];   // 8 MB  xn B-frags
__device__ uint2 g_attf[(size_t)BATCH * 512 * 32 * 32];  // 8 MB  att B-frags
__device__ uint4 g_wqf[(size_t)96 * 32 * 32];            // 1.5MB w_qkv A-frags
__device__ uint4 g_wpf[(size_t)32 * 32 * 32];            // 0.5MB w_proj A-frags

__device__ __forceinline__ uint32_t smem_u32(const void* p) {
    uint32_t a;
    asm("{ .reg .u64 t; cvta.to.shared.u64 t, %1; cvt.u32.u64 %0, t; }" : "=r"(a) : "l"(p));
    return a;
}
__device__ __forceinline__ uint32_t pack_bf16x2(float lo, float hi) {
    uint32_t d;
    asm("cvt.rn.bf16x2.f32 %0, %1, %2;" : "=r"(d) : "f"(hi), "f"(lo));
    return d;
}
__device__ __forceinline__ float ex2f(float x) {
    float r; asm("ex2.approx.ftz.f32 %0, %1;" : "=f"(r) : "f"(x)); return r;
}
#define MMA_BF16(d, a, b) \
    asm volatile("mma.sync.aligned.m16n8k16.row.col.f32.bf16.bf16.f32 " \
                 "{%0,%1,%2,%3}, {%4,%5,%6,%7}, {%8,%9}, {%0,%1,%2,%3};" \
                 : "+f"((d)[0]), "+f"((d)[1]), "+f"((d)[2]), "+f"((d)[3]) \
                 : "r"((a).x), "r"((a).y), "r"((a).z), "r"((a).w), \
                   "r"((b).x), "r"((b).y))

__device__ __forceinline__ void cp16(uint32_t dst, const void* src) {
    asm volatile("cp.async.cg.shared.global [%0], [%1], 16;" :: "r"(dst), "l"(src));
}
#define CP_COMMIT() asm volatile("cp.async.commit_group;" ::: "memory")
#define CP_WAIT(n)  asm volatile("cp.async.wait_group %0;" :: "n"(n) : "memory")

// ---------------- GroupNorm fused with xn fragment packing (R7 layout) ----------------
__global__ void __launch_bounds__(256) groupnorm_pack_kernel(const float* __restrict__ x,
                                                             const float* __restrict__ gw,
                                                             const float* __restrict__ gb,
                                                             uint2* __restrict__ Bf) {
    const int g = blockIdx.x, b = blockIdx.y;
    const int tid = threadIdx.x;
    const size_t base = ((size_t)b * C + g * CPG) * L;
    const int SPAN = CPG * L;
    const float* xr = x + base;
    const float4* x4 = (const float4*)xr;
    float s = 0.f, ss = 0.f;
    for (int i = tid; i < SPAN / 4; i += 256) {
        float4 v = x4[i];
        s  += v.x + v.y + v.z + v.w;
        ss += v.x * v.x + v.y * v.y + v.z * v.z + v.w * v.w;
    }
    __shared__ float rs[256], rss[256];
    rs[tid] = s; rss[tid] = ss;
    __syncthreads();
    for (int off = 128; off; off >>= 1) {
        if (tid < off) { rs[tid] += rs[tid + off]; rss[tid] += rss[tid + off]; }
        __syncthreads();
    }
    __shared__ float ga_s[CPG], be_s[CPG];
    if (tid < CPG) {
        float mean = rs[0] / SPAN;
        float var  = rss[0] / SPAN - mean * mean;
        float rstd = rsqrtf(var + EPS);
        float ga = gw[g * CPG + tid] * rstd;
        ga_s[tid] = ga;
        be_s[tid] = gb[g * CPG + tid] - mean * ga;
    }
    __syncthreads();

    uint2* dst = Bf + (size_t)b * 524288 + (size_t)g * 32;
    for (int i = tid; i < 16384; i += 256) {
        const int nt = i >> 5, lane = i & 31;
        const int gid = lane >> 2, tig = lane & 3;
        const int n = nt * 8 + gid;
        const int lc = 2 * tig;
        float v0 = xr[(size_t)lc * L + n]       * ga_s[lc]     + be_s[lc];
        float v1 = xr[(size_t)(lc + 1) * L + n] * ga_s[lc + 1] + be_s[lc + 1];
        float v8 = xr[(size_t)(lc + 8) * L + n] * ga_s[lc + 8] + be_s[lc + 8];
        float v9 = xr[(size_t)(lc + 9) * L + n] * ga_s[lc + 9] + be_s[lc + 9];
        uint2 o;
        o.x = pack_bf16x2(v0, v1);
        o.y = pack_bf16x2(v8, v9);
        dst[(size_t)nt * 1024 + lane] = o;
    }
}

// ---------------- weight packing ----------------
__global__ void __launch_bounds__(256) pack_w_kernel(const float* __restrict__ W,
                                                     uint4* __restrict__ Wf) {
    const int idx = blockIdx.x * 256 + threadIdx.x;
    const int blk = idx >> 5, lane = idx & 31;
    const int mt = blk >> 5, kt = blk & 31;
    const int gid = lane >> 2, tig = lane & 3;
    const float* r0 = W + (size_t)(mt * 16 + gid) * 512 + kt * 16;
    const float* r8 = r0 + 8 * 512;
    float2 a0 = *(const float2*)(r0 + 2 * tig);
    float2 a1 = *(const float2*)(r8 + 2 * tig);
    float2 a2 = *(const float2*)(r0 + 2 * tig + 8);
    float2 a3 = *(const float2*)(r8 + 2 * tig + 8);
    uint4 o;
    o.x = pack_bf16x2(a0.x, a0.y); o.y = pack_bf16x2(a1.x, a1.y);
    o.z = pack_bf16x2(a2.x, a2.y); o.w = pack_bf16x2(a3.x, a3.y);
    Wf[idx] = o;
}

// ---------------- QKV GEMM: 128 threads, warp=64mx64n, 2 CTAs/SM ----------------
#define QKV_SMEM 66560   // max(2 x 16KB staging, 128x130 fp32 T)

__global__ void __launch_bounds__(128) gemm_qkv_kernel(const uint4* __restrict__ Af,
                                                       const uint2* __restrict__ Bf,
                                                       const float* __restrict__ bias,
                                                       uint4* __restrict__ qf,
                                                       uint2* __restrict__ kf,
                                                       uint2* __restrict__ vf) {
    extern __shared__ char dynsm[];
    const uint32_t sb = smem_u32(dynsm);
    float* T = (float*)dynsm;
    const int tid = threadIdx.x, w = tid >> 5, l = tid & 31;
    const int mi2 = w >> 1, ni2 = w & 1, gid = l >> 2, tig = l & 3;
    const int nb = blockIdx.x, mb = blockIdx.y, bz = blockIdx.z;
    Bf += (size_t)bz * 524288;

    auto issue = [&](int kc, int s) {
        #pragma unroll
        for (int j = 0; j < 4; j++) {          // A: 512 x 16B
            const int e = tid + j * 128;
            const int bl = e >> 5, ln = e & 31;
            const int i = bl >> 1, ktl = bl & 1;
            cp16(sb + s * 16384 + e * 16,
                 (const char*)(Af + ((size_t)(mb * 8 + i) * 32 + kc * 2 + ktl) * 32 + ln));
        }
        #pragma unroll
        for (int j = 0; j < 4; j++) {          // B: 512 x 16B
            const int f = tid + j * 128;
            const int bl = f >> 4, lp = f & 15;
            const int nt = bl >> 1, ktl = bl & 1;
            cp16(sb + s * 16384 + 8192 + bl * 256 + lp * 16,
                 (const char*)Bf + ((size_t)(nb * 16 + nt) * 32 + kc * 2 + ktl) * 256 + lp * 16);
        }
    };

    issue(0, 0); CP_COMMIT();
    float acc[4][8][4] = {};
    for (int t = 0; t < 16; t++) {
        CP_WAIT(0);
        __syncthreads();
        if (t + 1 < 16) { issue(t + 1, (t + 1) & 1); CP_COMMIT(); }
        const int s = t & 1;
        #pragma unroll
        for (int ktl = 0; ktl < 2; ktl++) {
            uint4 A[4];
            #pragma unroll
            for (int mf = 0; mf < 4; mf++)
                A[mf] = *(const uint4*)(dynsm + s * 16384 +
                                        (((mi2 * 4 + mf) * 2 + ktl) * 32 + l) * 16);
            #pragma unroll
            for (int nt = 0; nt < 8; nt++) {
                uint2 B = *(const uint2*)(dynsm + s * 16384 + 8192 +
                                          (((ni2 * 8 + nt) * 2 + ktl) * 32 + l) * 8);
                #pragma unroll
                for (int mf = 0; mf < 4; mf++) MMA_BF16(acc[mf][nt], A[mf], B);
            }
        }
    }
    __syncthreads();   // staging dead before T overwrites it

    const int sec = mb >> 2, h = mb & 3;
    const int bh = bz * NH + h;
    // Q scale folds 1/sqrt(128) * log2(e) so attention can use raw ex2
    const float qs = (sec == 0) ? (0.08838834764831845f * 1.4426950408889634f) : 1.0f;

    #pragma unroll
    for (int mf = 0; mf < 4; mf++) {
        const int m0 = mi2 * 64 + mf * 16 + gid;
        const float b0v = bias[mb * 128 + m0], b8v = bias[mb * 128 + m0 + 8];
        #pragma unroll
        for (int nt = 0; nt < 8; nt++) {
            const int n0 = ni2 * 64 + nt * 8 + 2 * tig;
            T[m0 * 130 + n0]           = (acc[mf][nt][0] + b0v) * qs;
            T[m0 * 130 + n0 + 1]       = (acc[mf][nt][1] + b0v) * qs;
            T[(m0 + 8) * 130 + n0]     = (acc[mf][nt][2] + b8v) * qs;
            T[(m0 + 8) * 130 + n0 + 1] = (acc[mf][nt][3] + b8v) * qs;
        }
    }
    __syncthreads();

    if (sec == 0) {
        // Q A-frags: qf[(bh*32 + nb)*2048 + (mtb*8 + ktc)*32 + ln]
        uint4* dst = qf + ((size_t)bh * 32 + nb) * 2048;
        #pragma unroll
        for (int it = 0; it < 16; it++) {
            const int idx = tid + it * 128;
            const int blk = idx >> 5, ln = idx & 31;
            const int mtb = blk >> 3, ktc = blk & 7;
            const int g2 = ln >> 2, t2 = ln & 3;
            const int q = mtb * 16 + g2, c = ktc * 16 + 2 * t2;
            uint4 o;
            o.x = pack_bf16x2(T[c * 130 + q],           T[(c + 1) * 130 + q]);
            o.y = pack_bf16x2(T[c * 130 + q + 8],       T[(c + 1) * 130 + q + 8]);
            o.z = pack_bf16x2(T[(c + 8) * 130 + q],     T[(c + 9) * 130 + q]);
            o.w = pack_bf16x2(T[(c + 8) * 130 + q + 8], T[(c + 9) * 130 + q + 8]);
            dst[idx] = o;
        }
    } else if (sec == 1) {
        // K B-frags: kf[bh*131072 + nb*4096 + (ktc*16 + ntb)*32 + ln]
        uint2* dst = kf + (size_t)bh * 131072 + (size_t)nb * 4096;
        #pragma unroll
        for (int it = 0; it < 32; it++) {
            const int idx = tid + it * 128;
            const int blk = idx >> 5, ln = idx & 31;
            const int ktc = blk >> 4, ntb = blk & 15;
            const int g2 = ln >> 2, t2 = ln & 3;
            const int key = ntb * 8 + g2, c0 = ktc * 16 + 2 * t2;
            uint2 o;
            o.x = pack_bf16x2(T[c0 * 130 + key],       T[(c0 + 1) * 130 + key]);
            o.y = pack_bf16x2(T[(c0 + 8) * 130 + key], T[(c0 + 9) * 130 + key]);
            dst[idx] = o;
        }
    } else {
        // V B-frags: vf[bh*131072 + nb*4096 + (ktk*16 + ntb)*32 + ln]
        uint2* dst = vf + (size_t)bh * 131072 + (size_t)nb * 4096;
        #pragma unroll
        for (int it = 0; it < 32; it++) {
            const int idx = tid + it * 128;
            const int blk = idx >> 5, ln = idx & 31;
            const int ktk = blk >> 4, ntb = blk & 15;
            const int g2 = ln >> 2, t2 = ln & 3;
            const int hd = ntb * 8 + g2, key0 = ktk * 16 + 2 * t2;
            uint2 o;
            o.x = pack_bf16x2(T[hd * 130 + key0],     T[hd * 130 + key0 + 1]);
            o.y = pack_bf16x2(T[hd * 130 + key0 + 8], T[hd * 130 + key0 + 9]);
            dst[idx] = o;
        }
    }
}

// ---------------- proj GEMM: 128 threads, warp=64mx64n ----------------
#define PROJ_SMEM 32768

__global__ void __launch_bounds__(128) gemm_bf16_kernel(const uint4* __restrict__ Af,
                                                        const uint2* __restrict__ Bf,
                                                        const float* __restrict__ bias,
                                                        const float* __restrict__ resid,
                                                        float* __restrict__ out, int M) {
    extern __shared__ char psm[];
    const uint32_t sb = smem_u32(psm);
    const int tid = threadIdx.x, w = tid >> 5, l = tid & 31;
    const int mi2 = w >> 1, ni2 = w & 1, gid = l >> 2, tig = l & 3;
    const int nb = blockIdx.x, mb = blockIdx.y, bz = blockIdx.z;
    Bf += (size_t)bz * 524288;
    out += (size_t)bz * M * L;
    if (resid) resid += (size_t)bz * M * L;

    auto issue = [&](int kc, int s) {
        #pragma unroll
        for (int j = 0; j < 4; j++) {
            const int e = tid + j * 128;
            const int bl = e >> 5, ln = e & 31;
            const int i = bl >> 1, ktl = bl & 1;
            cp16(sb + s * 16384 + e * 16,
                 (const char*)(Af + ((size_t)(mb * 8 + i) * 32 + kc * 2 + ktl) * 32 + ln));
        }
        #pragma unroll
        for (int j = 0; j < 4; j++) {
            const int f = tid + j * 128;
            const int bl = f >> 4, lp = f & 15;
            const int nt = bl >> 1, ktl = bl & 1;
            cp16(sb + s * 16384 + 8192 + bl * 256 + lp * 16,
                 (const char*)Bf + ((size_t)(nb * 16 + nt) * 32 + kc * 2 + ktl) * 256 + lp * 16);
        }
    };

    issue(0, 0); CP_COMMIT();
    float acc[4][8][4] = {};
    for (int t = 0; t < 16; t++) {
        CP_WAIT(0);
        __syncthreads();
        if (t + 1 < 16) { issue(t + 1, (t + 1) & 1); CP_COMMIT(); }
        const int s = t & 1;
        #pragma unroll
        for (int ktl = 0; ktl < 2; ktl++) {
            uint4 A[4];
            #pragma unroll
            for (int mf = 0; mf < 4; mf++)
                A[mf] = *(const uint4*)(psm + s * 16384 +
                                        (((mi2 * 4 + mf) * 2 + ktl) * 32 + l) * 16);
            #pragma unroll
            for (int nt = 0; nt < 8; nt++) {
                uint2 B = *(const uint2*)(psm + s * 16384 + 8192 +
                                          (((ni2 * 8 + nt) * 2 + ktl) * 32 + l) * 8);
                #pragma unroll
                for (int mf = 0; mf < 4; mf++) MMA_BF16(acc[mf][nt], A[mf], B);
            }
        }
    }

    #pragma unroll
    for (int mf = 0; mf < 4; mf++) {
        const int m0 = mb * 128 + mi2 * 64 + mf * 16 + gid;
        const float b0v = bias[m0], b8v = bias[m0 + 8];
        #pragma unroll
        for (int nt = 0; nt < 8; nt++) {
            const int n0 = nb * 128 + ni2 * 64 + nt * 8 + 2 * tig;
            const size_t o0 = (size_t)m0 * L + n0, o8 = (size_t)(m0 + 8) * L + n0;
            float2 v0 = make_float2(acc[mf][nt][0] + b0v, acc[mf][nt][1] + b0v);
            float2 v8 = make_float2(acc[mf][nt][2] + b8v, acc[mf][nt][3] + b8v);
            if (resid) {
                float2 r0 = *(const float2*)(resid + o0);
                float2 r8 = *(const float2*)(resid + o8);
                v0.x += r0.x; v0.y += r0.y; v8.x += r8.x; v8.y += r8.y;
            }
            *(float2*)(out + o0) = v0;
            *(float2*)(out + o8) = v8;
        }
    }
}

// ---------------- attention (R7 structure, ex2 softmax) ----------------
// Warp (qi, kh): 32 queries, key half kh (64 keys) -> partial O over full 128 hd.
// smem: Q 32K | K 2x32K | V 2x32K = 160KB; Ob overlays Q/K at the end.
#define SM_K0 32768
#define SM_V0 98304
#define ATT_SMEM 163840

__global__ void __launch_bounds__(256) attn_bf16_kernel(const uint4* __restrict__ qf,
                                                        const uint2* __restrict__ kf,
                                                        const uint2* __restrict__ vf,
                                                        uint2* __restrict__ attf) {
    extern __shared__ char sm[];
    const uint32_t sb = smem_u32(sm);
    __shared__ float lsum_s[2][128];

    const int tid = threadIdx.x, w = tid >> 5, l = tid & 31;
    const int qi = w >> 1, kh = w & 1;
    const int gid = l >> 2, tig = l & 3;
    const int qb = blockIdx.x, bh = blockIdx.y;
    const int b = bh >> 2, h = bh & 3;

    const char* qsrc = (const char*)(qf + ((size_t)bh * 32 + qb) * 2048);
    const char* ksrc = (const char*)(kf + (size_t)bh * 131072);
    const char* vsrc = (const char*)(vf + (size_t)bh * 131072);

    #pragma unroll
    for (int j = 0; j < 8; j++) {
        const int i = tid + j * 256;
        cp16(sb + i * 16, qsrc + i * 16);
        cp16(sb + SM_K0 + i * 16, ksrc + i * 16);
        cp16(sb + SM_V0 + i * 16, vsrc + i * 16);
    }
    CP_COMMIT();

    float oacc[2][16][4] = {};
    float lsum[2][2] = {};

    for (int t = 0; t < 32; t++) {
        CP_WAIT(0);
        __syncthreads();
        if (t + 1 < 32) {
            const int pb = (t + 1) & 1;
            const char* kp = ksrc + (size_t)(t + 1) * 32768;
            const char* vp = vsrc + (size_t)(t + 1) * 32768;
            #pragma unroll
            for (int j = 0; j < 8; j++) {
                const int i = tid + j * 256;
                cp16(sb + SM_K0 + pb * 32768 + i * 16, kp + i * 16);
                cp16(sb + SM_V0 + pb * 32768 + i * 16, vp + i * 16);
            }
            CP_COMMIT();
        }

        const uint32_t Kb = SM_K0 + (t & 1) * 32768;
        // ---- S = Q K^T (warp: 32q x its 64-key half) ----
        float sacc[2][8][4] = {};
        #pragma unroll
        for (int ktc = 0; ktc < 8; ktc++) {
            uint4 A0 = *(const uint4*)(sm + (((qi * 2 + 0) * 8 + ktc) * 32 + l) * 16);
            uint4 A1 = *(const uint4*)(sm + (((qi * 2 + 1) * 8 + ktc) * 32 + l) * 16);
            #pragma unroll
            for (int nt = 0; nt < 8; nt++) {
                uint2 B = *(const uint2*)(sm + Kb + ((ktc * 16 + kh * 8 + nt) * 32 + l) * 8);
                MMA_BF16(sacc[0][nt], A0, B);
                MMA_BF16(sacc[1][nt], A1, B);
            }
        }

        // ---- ex2 (scale pre-folded with log2e) + pack P into A-frag registers ----
        uint4 pP[2][4];
        #pragma unroll
        for (int mt = 0; mt < 2; mt++) {
            #pragma unroll
            for (int kc = 0; kc < 4; kc++) {
                const int nt0 = 2 * kc, nt1 = 2 * kc + 1;
                float p00 = ex2f(sacc[mt][nt0][0]), p01 = ex2f(sacc[mt][nt0][1]);
                float p02 = ex2f(sacc[mt][nt0][2]), p03 = ex2f(sacc[mt][nt0][3]);
                float p10 = ex2f(sacc[mt][nt1][0]), p11 = ex2f(sacc[mt][nt1][1]);
                float p12 = ex2f(sacc[mt][nt1][2]), p13 = ex2f(sacc[mt][nt1][3]);
                lsum[mt][0] += p00 + p01 + p10 + p11;
                lsum[mt][1] += p02 + p03 + p12 + p13;
                pP[mt][kc].x = pack_bf16x2(p00, p01);
                pP[mt][kc].y = pack_bf16x2(p02, p03);
                pP[mt][kc].z = pack_bf16x2(p10, p11);
                pP[mt][kc].w = pack_bf16x2(p12, p13);
            }
        }

        // ---- O += P V over this warp's 64 keys, all 128 hd ----
        const uint32_t Vb = SM_V0 + (t & 1) * 32768;
        #pragma unroll
        for (int kt = 0; kt < 4; kt++) {
            const uint4 A0 = pP[0][kt], A1 = pP[1][kt];
            #pragma unroll
            for (int nt = 0; nt < 16; nt++) {
                uint2 B = *(const uint2*)(sm + Vb + (((kh * 4 + kt) * 16 + nt) * 32 + l) * 8);
                MMA_BF16(oacc[0][nt], A0, B);
                MMA_BF16(oacc[1][nt], A1, B);
            }
        }
    }

    // ---- lsum quad-reduce, publish per key-half ----
    #pragma unroll
    for (int mt = 0; mt < 2; mt++)
        #pragma unroll
        for (int dr = 0; dr < 2; dr++) {
            float v = lsum[mt][dr];
            v += __shfl_xor_sync(0xffffffffu, v, 1);
            v += __shfl_xor_sync(0xffffffffu, v, 2);
            lsum[mt][dr] = v;
        }
    __syncthreads();   // all compute done; smem free for Ob
    float* Ob = (float*)sm;   // [128 hd][stride 132] fp32
    if (tig == 0) {
        #pragma unroll
        for (int mt = 0; mt < 2; mt++)
            #pragma unroll
            for (int dr = 0; dr < 2; dr++)
                lsum_s[kh][qi * 32 + mt * 16 + gid + 8 * dr] = lsum[mt][dr];
    }
    if (kh == 0) {
        #pragma unroll
        for (int mt = 0; mt < 2; mt++)
            #pragma unroll
            for (int nt = 0; nt < 16; nt++)
                #pragma unroll
                for (int j = 0; j < 4; j++) {
                    const int q  = qi * 32 + mt * 16 + gid + 8 * (j >> 1);
                    const int hd = nt * 8 + tig * 2 + (j & 1);
                    Ob[hd * 132 + q] = oacc[mt][nt][j];
                }
    }
    __syncthreads();
    if (kh == 1) {
        #pragma unroll
        for (int mt = 0; mt < 2; mt++)
            #pragma unroll
            for (int nt = 0; nt < 16; nt++)
                #pragma unroll
                for (int j = 0; j < 4; j++) {
                    const int q  = qi * 32 + mt * 16 + gid + 8 * (j >> 1);
                    const int hd = nt * 8 + tig * 2 + (j & 1);
                    Ob[hd * 132 + q] += oacc[mt][nt][j];
                }
    }
    __syncthreads();

    // ---- pack proj B-frags with normalization ----
    const size_t attbase = (size_t)b * 524288;
    #pragma unroll
    for (int it = 0; it < 16; it++) {
        const int slot = tid + it * 256;
        const int lb = slot >> 5, ln = slot & 31;
        const int ntl = lb >> 3, ktl = lb & 7;
        const int g2 = ln >> 2, t2 = ln & 3;
        const int cl = ktl * 16 + 2 * t2;
        const int ql = ntl * 8 + g2;
        const float linv = 1.0f / (lsum_s[0][ql] + lsum_s[1][ql]);
        uint2 o;
        o.x = pack_bf16x2(Ob[cl * 132 + ql] * linv,       Ob[(cl + 1) * 132 + ql] * linv);
        o.y = pack_bf16x2(Ob[(cl + 8) * 132 + ql] * linv, Ob[(cl + 9) * 132 + ql] * linv);
        attf[attbase + ((size_t)(qb * 16 + ntl) * 32 + (h * 8 + ktl)) * 32 + ln] = o;
    }
}

// ---------------- host ----------------
extern "C" void kernel_launch(void* const* d_in, const int* in_sizes, int n_in,
                              void* d_out, int out_size) {
    const float* x      = (const float*)d_in[0];
    const float* gn_w   = (const float*)d_in[1];
    const float* gn_b   = (const float*)d_in[2];
    const float* w_qkv  = (const float*)d_in[3];
    const float* b_qkv  = (const float*)d_in[4];
    const float* w_proj = (const float*)d_in[5];
    const float* b_proj = (const float*)d_in[6];
    float* out = (float*)d_out;

    uint4 *qf_p, *wqf_p, *wpf_p;
    uint2 *kf_p, *vf_p, *xnf_p, *attf_p;
    cudaGetSymbolAddress((void**)&qf_p, g_qf);
    cudaGetSymbolAddress((void**)&kf_p, g_kf);
    cudaGetSymbolAddress((void**)&vf_p, g_vf);
    cudaGetSymbolAddress((void**)&xnf_p, g_xnf);
    cudaGetSymbolAddress((void**)&attf_p, g_attf);
    cudaGetSymbolAddress((void**)&wqf_p, g_wqf);
    cudaGetSymbolAddress((void**)&wpf_p, g_wpf);

    // 1) GroupNorm fused with xn fragment packing; weight packing
    groupnorm_pack_kernel<<<dim3(GROUPS, BATCH), 256>>>(x, gn_w, gn_b, xnf_p);
    pack_w_kernel<<<384, 256>>>(w_qkv, wqf_p);
    pack_w_kernel<<<128, 256>>>(w_proj, wpf_p);

    // 2) QKV GEMM (128 threads, 64x64 warps) with fused q/k/v fragment epilogue
    cudaFuncSetAttribute(gemm_qkv_kernel, cudaFuncAttributeMaxDynamicSharedMemorySize, QKV_SMEM);
    gemm_qkv_kernel<<<dim3(32, 12, BATCH), 128, QKV_SMEM>>>(wqf_p, xnf_p, b_qkv,
                                                            qf_p, kf_p, vf_p);

    // 3) attention (128-key tiles, register P), emits proj B-frags
    cudaFuncSetAttribute(attn_bf16_kernel, cudaFuncAttributeMaxDynamicSharedMemorySize, ATT_SMEM);
    attn_bf16_kernel<<<dim3(L / 128, BATCH * NH), 256, ATT_SMEM>>>(qf_p, kf_p, vf_p, attf_p);

    // 4) proj GEMM (128 threads, 64x64 warps) + bias + residual -> out
    cudaFuncSetAttribute(gemm_bf16_kernel, cudaFuncAttributeMaxDynamicSharedMemorySize, PROJ_SMEM);
    gemm_bf16_kernel<<<dim3(32, 4, BATCH), 128, PROJ_SMEM>>>(wpf_p, attf_p, b_proj, x, out, C);
}

// round 11
// speedup vs baseline: 1.0691x; 1.0091x over previous
#include <cuda_runtime.h>
#include <math.h>
#include <stdint.h>

#define BATCH 2
#define C 512
#define L 4096
#define NH 4
#define HD 128
#define GROUPS 32
#define CPG (C / GROUPS)   // 16
#define EPS 1e-5f
#define GN_SPL 4

// ---------------- scratch (static device globals; no allocation) ----------------
__device__ uint4 g_qf[(size_t)BATCH * NH * 32 * 2048];   // 8 MB  Q A-frags
__device__ uint2 g_kf[(size_t)BATCH * NH * 32 * 4096];   // 8 MB  K B-frags
__device__ uint2 g_vf[(size_t)BATCH * NH * 32 * 4096];   // 8 MB  V B-frags
__device__ uint2 g_xnf[(size_t)BATCH * 512 * 32 * 32];   // 8 MB  xn B-frags
__device__ uint2 g_attf[(size_t)BATCH * 512 * 32 * 32];  // 8 MB  att B-frags
__device__ uint4 g_wqf[(size_t)96 * 32 * 32];            // 1.5MB w_qkv A-frags
__device__ uint4 g_wpf[(size_t)32 * 32 * 32];            // 0.5MB w_proj A-frags
__device__ float2 g_gnpart[BATCH][GROUPS][GN_SPL];       // GN partial (sum, sumsq)

__device__ __forceinline__ uint32_t smem_u32(const void* p) {
    uint32_t a;
    asm("{ .reg .u64 t; cvta.to.shared.u64 t, %1; cvt.u32.u64 %0, t; }" : "=r"(a) : "l"(p));
    return a;
}
__device__ __forceinline__ uint32_t pack_bf16x2(float lo, float hi) {
    uint32_t d;
    asm("cvt.rn.bf16x2.f32 %0, %1, %2;" : "=r"(d) : "f"(hi), "f"(lo));
    return d;
}
__device__ __forceinline__ float ex2f(float x) {
    float r; asm("ex2.approx.ftz.f32 %0, %1;" : "=f"(r) : "f"(x)); return r;
}
#define MMA_BF16(d, a, b) \
    asm volatile("mma.sync.aligned.m16n8k16.row.col.f32.bf16.bf16.f32 " \
                 "{%0,%1,%2,%3}, {%4,%5,%6,%7}, {%8,%9}, {%0,%1,%2,%3};" \
                 : "+f"((d)[0]), "+f"((d)[1]), "+f"((d)[2]), "+f"((d)[3]) \
                 : "r"((a).x), "r"((a).y), "r"((a).z), "r"((a).w), \
                   "r"((b).x), "r"((b).y))

__device__ __forceinline__ void cp16(uint32_t dst, const void* src) {
    asm volatile("cp.async.cg.shared.global [%0], [%1], 16;" :: "r"(dst), "l"(src));
}
#define CP_COMMIT() asm volatile("cp.async.commit_group;" ::: "memory")
#define CP_WAIT(n)  asm volatile("cp.async.wait_group %0;" :: "n"(n) : "memory")

// ---------------- GN pass 1: per-slice partial sums ----------------
__global__ void __launch_bounds__(256) gn_stats_kernel(const float* __restrict__ x) {
    const int g = blockIdx.x, b = blockIdx.y, z = blockIdx.z;
    const int tid = threadIdx.x;
    const size_t base = ((size_t)b * C + g * CPG) * L;
    const int QSPAN4 = (CPG * L) / (4 * GN_SPL);   // float4 count per slice = 4096
    const float4* x4 = (const float4*)(x + base) + (size_t)z * QSPAN4;
    float s = 0.f, ss = 0.f;
    for (int i = tid; i < QSPAN4; i += 256) {
        float4 v = x4[i];
        s  += v.x + v.y + v.z + v.w;
        ss += v.x * v.x + v.y * v.y + v.z * v.z + v.w * v.w;
    }
    __shared__ float rs[256], rss[256];
    rs[tid] = s; rss[tid] = ss;
    __syncthreads();
    for (int off = 128; off; off >>= 1) {
        if (tid < off) { rs[tid] += rs[tid + off]; rss[tid] += rss[tid + off]; }
        __syncthreads();
    }
    if (tid == 0) g_gnpart[b][g][z] = make_float2(rs[0], rss[0]);
}

// ---------------- GN pass 2: normalize + emit xn B-frags (slice z of nt range) ----------------
__global__ void __launch_bounds__(256) gn_apply_kernel(const float* __restrict__ x,
                                                       const float* __restrict__ gw,
                                                       const float* __restrict__ gb,
                                                       uint2* __restrict__ Bf) {
    const int g = blockIdx.x, b = blockIdx.y, z = blockIdx.z;
    const int tid = threadIdx.x;
    const size_t base = ((size_t)b * C + g * CPG) * L;
    const float* xr = x + base;
    const int SPAN = CPG * L;

    __shared__ float ga_s[CPG], be_s[CPG];
    if (tid < CPG) {
        float s = 0.f, ss = 0.f;
        #pragma unroll
        for (int zz = 0; zz < GN_SPL; zz++) {
            float2 p = g_gnpart[b][g][zz];
            s += p.x; ss += p.y;
        }
        float mean = s / SPAN;
        float var  = ss / SPAN - mean * mean;
        float rstd = rsqrtf(var + EPS);
        float ga = gw[g * CPG + tid] * rstd;
        ga_s[tid] = ga;
        be_s[tid] = gb[g * CPG + tid] - mean * ga;
    }
    __syncthreads();

    uint2* dst = Bf + (size_t)b * 524288 + (size_t)g * 32;
    const int i0 = z * (16384 / GN_SPL);
    for (int i = i0 + tid; i < i0 + 16384 / GN_SPL; i += 256) {
        const int nt = i >> 5, lane = i & 31;
        const int gid = lane >> 2, tig = lane & 3;
        const int n = nt * 8 + gid;
        const int lc = 2 * tig;
        float v0 = xr[(size_t)lc * L + n]       * ga_s[lc]     + be_s[lc];
        float v1 = xr[(size_t)(lc + 1) * L + n] * ga_s[lc + 1] + be_s[lc + 1];
        float v8 = xr[(size_t)(lc + 8) * L + n] * ga_s[lc + 8] + be_s[lc + 8];
        float v9 = xr[(size_t)(lc + 9) * L + n] * ga_s[lc + 9] + be_s[lc + 9];
        uint2 o;
        o.x = pack_bf16x2(v0, v1);
        o.y = pack_bf16x2(v8, v9);
        dst[(size_t)nt * 1024 + lane] = o;
    }
}

// ---------------- weight packing ----------------
__global__ void __launch_bounds__(256) pack_w_kernel(const float* __restrict__ W,
                                                     uint4* __restrict__ Wf) {
    const int idx = blockIdx.x * 256 + threadIdx.x;
    const int blk = idx >> 5, lane = idx & 31;
    const int mt = blk >> 5, kt = blk & 31;
    const int gid = lane >> 2, tig = lane & 3;
    const float* r0 = W + (size_t)(mt * 16 + gid) * 512 + kt * 16;
    const float* r8 = r0 + 8 * 512;
    float2 a0 = *(const float2*)(r0 + 2 * tig);
    float2 a1 = *(const float2*)(r8 + 2 * tig);
    float2 a2 = *(const float2*)(r0 + 2 * tig + 8);
    float2 a3 = *(const float2*)(r8 + 2 * tig + 8);
    uint4 o;
    o.x = pack_bf16x2(a0.x, a0.y); o.y = pack_bf16x2(a1.x, a1.y);
    o.z = pack_bf16x2(a2.x, a2.y); o.w = pack_bf16x2(a3.x, a3.y);
    Wf[idx] = o;
}

// ---------------- QKV GEMM: 128 threads, warp=64mx64n ----------------
#define QKV_SMEM 66560   // max(2 x 16KB staging, 128x130 fp32 T)

__global__ void __launch_bounds__(128) gemm_qkv_kernel(const uint4* __restrict__ Af,
                                                       const uint2* __restrict__ Bf,
                                                       const float* __restrict__ bias,
                                                       uint4* __restrict__ qf,
                                                       uint2* __restrict__ kf,
                                                       uint2* __restrict__ vf) {
    extern __shared__ char dynsm[];
    const uint32_t sb = smem_u32(dynsm);
    float* T = (float*)dynsm;
    const int tid = threadIdx.x, w = tid >> 5, l = tid & 31;
    const int mi2 = w >> 1, ni2 = w & 1, gid = l >> 2, tig = l & 3;
    const int nb = blockIdx.x, mb = blockIdx.y, bz = blockIdx.z;
    Bf += (size_t)bz * 524288;

    auto issue = [&](int kc, int s) {
        #pragma unroll
        for (int j = 0; j < 4; j++) {          // A: 512 x 16B
            const int e = tid + j * 128;
            const int bl = e >> 5, ln = e & 31;
            const int i = bl >> 1, ktl = bl & 1;
            cp16(sb + s * 16384 + e * 16,
                 (const char*)(Af + ((size_t)(mb * 8 + i) * 32 + kc * 2 + ktl) * 32 + ln));
        }
        #pragma unroll
        for (int j = 0; j < 4; j++) {          // B: 512 x 16B
            const int f = tid + j * 128;
            const int bl = f >> 4, lp = f & 15;
            const int nt = bl >> 1, ktl = bl & 1;
            cp16(sb + s * 16384 + 8192 + bl * 256 + lp * 16,
                 (const char*)Bf + ((size_t)(nb * 16 + nt) * 32 + kc * 2 + ktl) * 256 + lp * 16);
        }
    };

    issue(0, 0); CP_COMMIT();
    float acc[4][8][4] = {};
    for (int t = 0; t < 16; t++) {
        CP_WAIT(0);
        __syncthreads();
        if (t + 1 < 16) { issue(t + 1, (t + 1) & 1); CP_COMMIT(); }
        const int s = t & 1;
        #pragma unroll
        for (int ktl = 0; ktl < 2; ktl++) {
            uint4 A[4];
            #pragma unroll
            for (int mf = 0; mf < 4; mf++)
                A[mf] = *(const uint4*)(dynsm + s * 16384 +
                                        (((mi2 * 4 + mf) * 2 + ktl) * 32 + l) * 16);
            #pragma unroll
            for (int nt = 0; nt < 8; nt++) {
                uint2 B = *(const uint2*)(dynsm + s * 16384 + 8192 +
                                          (((ni2 * 8 + nt) * 2 + ktl) * 32 + l) * 8);
                #pragma unroll
                for (int mf = 0; mf < 4; mf++) MMA_BF16(acc[mf][nt], A[mf], B);
            }
        }
    }
    __syncthreads();   // staging dead before T overwrites it

    const int sec = mb >> 2, h = mb & 3;
    const int bh = bz * NH + h;
    // Q scale folds 1/sqrt(128) * log2(e) so attention can use raw ex2
    const float qs = (sec == 0) ? (0.08838834764831845f * 1.4426950408889634f) : 1.0f;

    #pragma unroll
    for (int mf = 0; mf < 4; mf++) {
        const int m0 = mi2 * 64 + mf * 16 + gid;
        const float b0v = bias[mb * 128 + m0], b8v = bias[mb * 128 + m0 + 8];
        #pragma unroll
        for (int nt = 0; nt < 8; nt++) {
            const int n0 = ni2 * 64 + nt * 8 + 2 * tig;
            T[m0 * 130 + n0]           = (acc[mf][nt][0] + b0v) * qs;
            T[m0 * 130 + n0 + 1]       = (acc[mf][nt][1] + b0v) * qs;
            T[(m0 + 8) * 130 + n0]     = (acc[mf][nt][2] + b8v) * qs;
            T[(m0 + 8) * 130 + n0 + 1] = (acc[mf][nt][3] + b8v) * qs;
        }
    }
    __syncthreads();

    if (sec == 0) {
        uint4* dst = qf + ((size_t)bh * 32 + nb) * 2048;
        #pragma unroll
        for (int it = 0; it < 16; it++) {
            const int idx = tid + it * 128;
            const int blk = idx >> 5, ln = idx & 31;
            const int mtb = blk >> 3, ktc = blk & 7;
            const int g2 = ln >> 2, t2 = ln & 3;
            const int q = mtb * 16 + g2, c = ktc * 16 + 2 * t2;
            uint4 o;
            o.x = pack_bf16x2(T[c * 130 + q],           T[(c + 1) * 130 + q]);
            o.y = pack_bf16x2(T[c * 130 + q + 8],       T[(c + 1) * 130 + q + 8]);
            o.z = pack_bf16x2(T[(c + 8) * 130 + q],     T[(c + 9) * 130 + q]);
            o.w = pack_bf16x2(T[(c + 8) * 130 + q + 8], T[(c + 9) * 130 + q + 8]);
            dst[idx] = o;
        }
    } else if (sec == 1) {
        uint2* dst = kf + (size_t)bh * 131072 + (size_t)nb * 4096;
        #pragma unroll
        for (int it = 0; it < 32; it++) {
            const int idx = tid + it * 128;
            const int blk = idx >> 5, ln = idx & 31;
            const int ktc = blk >> 4, ntb = blk & 15;
            const int g2 = ln >> 2, t2 = ln & 3;
            const int key = ntb * 8 + g2, c0 = ktc * 16 + 2 * t2;
            uint2 o;
            o.x = pack_bf16x2(T[c0 * 130 + key],       T[(c0 + 1) * 130 + key]);
            o.y = pack_bf16x2(T[(c0 + 8) * 130 + key], T[(c0 + 9) * 130 + key]);
            dst[idx] = o;
        }
    } else {
        uint2* dst = vf + (size_t)bh * 131072 + (size_t)nb * 4096;
        #pragma unroll
        for (int it = 0; it < 32; it++) {
            const int idx = tid + it * 128;
            const int blk = idx >> 5, ln = idx & 31;
            const int ktk = blk >> 4, ntb = blk & 15;
            const int g2 = ln >> 2, t2 = ln & 3;
            const int hd = ntb * 8 + g2, key0 = ktk * 16 + 2 * t2;
            uint2 o;
            o.x = pack_bf16x2(T[hd * 130 + key0],     T[hd * 130 + key0 + 1]);
            o.y = pack_bf16x2(T[hd * 130 + key0 + 8], T[hd * 130 + key0 + 9]);
            dst[idx] = o;
        }
    }
}

// ---------------- proj GEMM: 128 threads, warp=64mx64n ----------------
#define PROJ_SMEM 32768

__global__ void __launch_bounds__(128) gemm_bf16_kernel(const uint4* __restrict__ Af,
                                                        const uint2* __restrict__ Bf,
                                                        const float* __restrict__ bias,
                                                        const float* __restrict__ resid,
                                                        float* __restrict__ out, int M) {
    extern __shared__ char psm[];
    const uint32_t sb = smem_u32(psm);
    const int tid = threadIdx.x, w = tid >> 5, l = tid & 31;
    const int mi2 = w >> 1, ni2 = w & 1, gid = l >> 2, tig = l & 3;
    const int nb = blockIdx.x, mb = blockIdx.y, bz = blockIdx.z;
    Bf += (size_t)bz * 524288;
    out += (size_t)bz * M * L;
    if (resid) resid += (size_t)bz * M * L;

    auto issue = [&](int kc, int s) {
        #pragma unroll
        for (int j = 0; j < 4; j++) {
            const int e = tid + j * 128;
            const int bl = e >> 5, ln = e & 31;
            const int i = bl >> 1, ktl = bl & 1;
            cp16(sb + s * 16384 + e * 16,
                 (const char*)(Af + ((size_t)(mb * 8 + i) * 32 + kc * 2 + ktl) * 32 + ln));
        }
        #pragma unroll
        for (int j = 0; j < 4; j++) {
            const int f = tid + j * 128;
            const int bl = f >> 4, lp = f & 15;
            const int nt = bl >> 1, ktl = bl & 1;
            cp16(sb + s * 16384 + 8192 + bl * 256 + lp * 16,
                 (const char*)Bf + ((size_t)(nb * 16 + nt) * 32 + kc * 2 + ktl) * 256 + lp * 16);
        }
    };

    issue(0, 0); CP_COMMIT();
    float acc[4][8][4] = {};
    for (int t = 0; t < 16; t++) {
        CP_WAIT(0);
        __syncthreads();
        if (t + 1 < 16) { issue(t + 1, (t + 1) & 1); CP_COMMIT(); }
        const int s = t & 1;
        #pragma unroll
        for (int ktl = 0; ktl < 2; ktl++) {
            uint4 A[4];
            #pragma unroll
            for (int mf = 0; mf < 4; mf++)
                A[mf] = *(const uint4*)(psm + s * 16384 +
                                        (((mi2 * 4 + mf) * 2 + ktl) * 32 + l) * 16);
            #pragma unroll
            for (int nt = 0; nt < 8; nt++) {
                uint2 B = *(const uint2*)(psm + s * 16384 + 8192 +
                                          (((ni2 * 8 + nt) * 2 + ktl) * 32 + l) * 8);
                #pragma unroll
                for (int mf = 0; mf < 4; mf++) MMA_BF16(acc[mf][nt], A[mf], B);
            }
        }
    }

    #pragma unroll
    for (int mf = 0; mf < 4; mf++) {
        const int m0 = mb * 128 + mi2 * 64 + mf * 16 + gid;
        const float b0v = bias[m0], b8v = bias[m0 + 8];
        #pragma unroll
        for (int nt = 0; nt < 8; nt++) {
            const int n0 = nb * 128 + ni2 * 64 + nt * 8 + 2 * tig;
            const size_t o0 = (size_t)m0 * L + n0, o8 = (size_t)(m0 + 8) * L + n0;
            float2 v0 = make_float2(acc[mf][nt][0] + b0v, acc[mf][nt][1] + b0v);
            float2 v8 = make_float2(acc[mf][nt][2] + b8v, acc[mf][nt][3] + b8v);
            if (resid) {
                float2 r0 = *(const float2*)(resid + o0);
                float2 r8 = *(const float2*)(resid + o8);
                v0.x += r0.x; v0.y += r0.y; v8.x += r8.x; v8.y += r8.y;
            }
            *(float2*)(out + o0) = v0;
            *(float2*)(out + o8) = v8;
        }
    }
}

// ---------------- attention (R7 structure, ex2 softmax) ----------------
#define SM_K0 32768
#define SM_V0 98304
#define ATT_SMEM 163840

__global__ void __launch_bounds__(256) attn_bf16_kernel(const uint4* __restrict__ qf,
                                                        const uint2* __restrict__ kf,
                                                        const uint2* __restrict__ vf,
                                                        uint2* __restrict__ attf) {
    extern __shared__ char sm[];
    const uint32_t sb = smem_u32(sm);
    __shared__ float lsum_s[2][128];

    const int tid = threadIdx.x, w = tid >> 5, l = tid & 31;
    const int qi = w >> 1, kh = w & 1;
    const int gid = l >> 2, tig = l & 3;
    const int qb = blockIdx.x, bh = blockIdx.y;
    const int b = bh >> 2, h = bh & 3;

    const char* qsrc = (const char*)(qf + ((size_t)bh * 32 + qb) * 2048);
    const char* ksrc = (const char*)(kf + (size_t)bh * 131072);
    const char* vsrc = (const char*)(vf + (size_t)bh * 131072);

    #pragma unroll
    for (int j = 0; j < 8; j++) {
        const int i = tid + j * 256;
        cp16(sb + i * 16, qsrc + i * 16);
        cp16(sb + SM_K0 + i * 16, ksrc + i * 16);
        cp16(sb + SM_V0 + i * 16, vsrc + i * 16);
    }
    CP_COMMIT();

    float oacc[2][16][4] = {};
    float lsum[2][2] = {};

    for (int t = 0; t < 32; t++) {
        CP_WAIT(0);
        __syncthreads();
        if (t + 1 < 32) {
            const int pb = (t + 1) & 1;
            const char* kp = ksrc + (size_t)(t + 1) * 32768;
            const char* vp = vsrc + (size_t)(t + 1) * 32768;
            #pragma unroll
            for (int j = 0; j < 8; j++) {
                const int i = tid + j * 256;
                cp16(sb + SM_K0 + pb * 32768 + i * 16, kp + i * 16);
                cp16(sb + SM_V0 + pb * 32768 + i * 16, vp + i * 16);
            }
            CP_COMMIT();
        }

        const uint32_t Kb = SM_K0 + (t & 1) * 32768;
        float sacc[2][8][4] = {};
        #pragma unroll
        for (int ktc = 0; ktc < 8; ktc++) {
            uint4 A0 = *(const uint4*)(sm + (((qi * 2 + 0) * 8 + ktc) * 32 + l) * 16);
            uint4 A1 = *(const uint4*)(sm + (((qi * 2 + 1) * 8 + ktc) * 32 + l) * 16);
            #pragma unroll
            for (int nt = 0; nt < 8; nt++) {
                uint2 B = *(const uint2*)(sm + Kb + ((ktc * 16 + kh * 8 + nt) * 32 + l) * 8);
                MMA_BF16(sacc[0][nt], A0, B);
                MMA_BF16(sacc[1][nt], A1, B);
            }
        }

        uint4 pP[2][4];
        #pragma unroll
        for (int mt = 0; mt < 2; mt++) {
            #pragma unroll
            for (int kc = 0; kc < 4; kc++) {
                const int nt0 = 2 * kc, nt1 = 2 * kc + 1;
                float p00 = ex2f(sacc[mt][nt0][0]), p01 = ex2f(sacc[mt][nt0][1]);
                float p02 = ex2f(sacc[mt][nt0][2]), p03 = ex2f(sacc[mt][nt0][3]);
                float p10 = ex2f(sacc[mt][nt1][0]), p11 = ex2f(sacc[mt][nt1][1]);
                float p12 = ex2f(sacc[mt][nt1][2]), p13 = ex2f(sacc[mt][nt1][3]);
                lsum[mt][0] += p00 + p01 + p10 + p11;
                lsum[mt][1] += p02 + p03 + p12 + p13;
                pP[mt][kc].x = pack_bf16x2(p00, p01);
                pP[mt][kc].y = pack_bf16x2(p02, p03);
                pP[mt][kc].z = pack_bf16x2(p10, p11);
                pP[mt][kc].w = pack_bf16x2(p12, p13);
            }
        }

        const uint32_t Vb = SM_V0 + (t & 1) * 32768;
        #pragma unroll
        for (int kt = 0; kt < 4; kt++) {
            const uint4 A0 = pP[0][kt], A1 = pP[1][kt];
            #pragma unroll
            for (int nt = 0; nt < 16; nt++) {
                uint2 B = *(const uint2*)(sm + Vb + (((kh * 4 + kt) * 16 + nt) * 32 + l) * 8);
                MMA_BF16(oacc[0][nt], A0, B);
                MMA_BF16(oacc[1][nt], A1, B);
            }
        }
    }

    #pragma unroll
    for (int mt = 0; mt < 2; mt++)
        #pragma unroll
        for (int dr = 0; dr < 2; dr++) {
            float v = lsum[mt][dr];
            v += __shfl_xor_sync(0xffffffffu, v, 1);
            v += __shfl_xor_sync(0xffffffffu, v, 2);
            lsum[mt][dr] = v;
        }
    __syncthreads();
    float* Ob = (float*)sm;
    if (tig == 0) {
        #pragma unroll
        for (int mt = 0; mt < 2; mt++)
            #pragma unroll
            for (int dr = 0; dr < 2; dr++)
                lsum_s[kh][qi * 32 + mt * 16 + gid + 8 * dr] = lsum[mt][dr];
    }
    if (kh == 0) {
        #pragma unroll
        for (int mt = 0; mt < 2; mt++)
            #pragma unroll
            for (int nt = 0; nt < 16; nt++)
                #pragma unroll
                for (int j = 0; j < 4; j++) {
                    const int q  = qi * 32 + mt * 16 + gid + 8 * (j >> 1);
                    const int hd = nt * 8 + tig * 2 + (j & 1);
                    Ob[hd * 132 + q] = oacc[mt][nt][j];
                }
    }
    __syncthreads();
    if (kh == 1) {
        #pragma unroll
        for (int mt = 0; mt < 2; mt++)
            #pragma unroll
            for (int nt = 0; nt < 16; nt++)
                #pragma unroll
                for (int j = 0; j < 4; j++) {
                    const int q  = qi * 32 + mt * 16 + gid + 8 * (j >> 1);
                    const int hd = nt * 8 + tig * 2 + (j & 1);
                    Ob[hd * 132 + q] += oacc[mt][nt][j];
                }
    }
    __syncthreads();

    const size_t attbase = (size_t)b * 524288;
    #pragma unroll
    for (int it = 0; it < 16; it++) {
        const int slot = tid + it * 256;
        const int lb = slot >> 5, ln = slot & 31;
        const int ntl = lb >> 3, ktl = lb & 7;
        const int g2 = ln >> 2, t2 = ln & 3;
        const int cl = ktl * 16 + 2 * t2;
        const int ql = ntl * 8 + g2;
        const float linv = 1.0f / (lsum_s[0][ql] + lsum_s[1][ql]);
        uint2 o;
        o.x = pack_bf16x2(Ob[cl * 132 + ql] * linv,       Ob[(cl + 1) * 132 + ql] * linv);
        o.y = pack_bf16x2(Ob[(cl + 8) * 132 + ql] * linv, Ob[(cl + 9) * 132 + ql] * linv);
        attf[attbase + ((size_t)(qb * 16 + ntl) * 32 + (h * 8 + ktl)) * 32 + ln] = o;
    }
}

// ---------------- host ----------------
extern "C" void kernel_launch(void* const* d_in, const int* in_sizes, int n_in,
                              void* d_out, int out_size) {
    const float* x      = (const float*)d_in[0];
    const float* gn_w   = (const float*)d_in[1];
    const float* gn_b   = (const float*)d_in[2];
    const float* w_qkv  = (const float*)d_in[3];
    const float* b_qkv  = (const float*)d_in[4];
    const float* w_proj = (const float*)d_in[5];
    const float* b_proj = (const float*)d_in[6];
    float* out = (float*)d_out;

    uint4 *qf_p, *wqf_p, *wpf_p;
    uint2 *kf_p, *vf_p, *xnf_p, *attf_p;
    cudaGetSymbolAddress((void**)&qf_p, g_qf);
    cudaGetSymbolAddress((void**)&kf_p, g_kf);
    cudaGetSymbolAddress((void**)&vf_p, g_vf);
    cudaGetSymbolAddress((void**)&xnf_p, g_xnf);
    cudaGetSymbolAddress((void**)&attf_p, g_attf);
    cudaGetSymbolAddress((void**)&wqf_p, g_wqf);
    cudaGetSymbolAddress((void**)&wpf_p, g_wpf);

    // 1) GN stats (whole-chip parallel) + weight packing + GN apply/pack
    gn_stats_kernel<<<dim3(GROUPS, BATCH, GN_SPL), 256>>>(x);
    pack_w_kernel<<<384, 256>>>(w_qkv, wqf_p);
    pack_w_kernel<<<128, 256>>>(w_proj, wpf_p);
    gn_apply_kernel<<<dim3(GROUPS, BATCH, GN_SPL), 256>>>(x, gn_w, gn_b, xnf_p);

    // 2) QKV GEMM (128 threads, 64x64 warps) with fused q/k/v fragment epilogue
    cudaFuncSetAttribute(gemm_qkv_kernel, cudaFuncAttributeMaxDynamicSharedMemorySize, QKV_SMEM);
    gemm_qkv_kernel<<<dim3(32, 12, BATCH), 128, QKV_SMEM>>>(wqf_p, xnf_p, b_qkv,
                                                            qf_p, kf_p, vf_p);

    // 3) attention (128-key tiles, register P), emits proj B-frags
    cudaFuncSetAttribute(attn_bf16_kernel, cudaFuncAttributeMaxDynamicSharedMemorySize, ATT_SMEM);
    attn_bf16_kernel<<<dim3(L / 128, BATCH * NH), 256, ATT_SMEM>>>(qf_p, kf_p, vf_p, attf_p);

    // 4) proj GEMM (128 threads, 64x64 warps) + bias + residual -> out
    cudaFuncSetAttribute(gemm_bf16_kernel, cudaFuncAttributeMaxDynamicSharedMemorySize, PROJ_SMEM);
    gemm_bf16_kernel<<<dim3(32, 4, BATCH), 128, PROJ_SMEM>>>(wpf_p, attf_p, b_proj, x, out, C);
}

// round 12
// speedup vs baseline: 1.1019x; 1.0307x over previous
#include <cuda_runtime.h>
#include <math.h>
#include <stdint.h>

#define BATCH 2
#define C 512
#define L 4096
#define NH 4
#define HD 128
#define GROUPS 32
#define CPG (C / GROUPS)   // 16
#define EPS 1e-5f
#define GN_SPL 8

// ---------------- scratch (static device globals; no allocation) ----------------
__device__ uint4 g_qf[(size_t)BATCH * NH * 32 * 2048];   // 8 MB  Q A-frags
__device__ uint2 g_kf[(size_t)BATCH * NH * 32 * 4096];   // 8 MB  K B-frags
__device__ uint2 g_vf[(size_t)BATCH * NH * 32 * 4096];   // 8 MB  V B-frags
__device__ uint2 g_xnf[(size_t)BATCH * 512 * 32 * 32];   // 8 MB  xn B-frags
__device__ uint2 g_attf[(size_t)BATCH * 512 * 32 * 32];  // 8 MB  att B-frags
__device__ uint4 g_wqf[(size_t)96 * 32 * 32];            // 1.5MB w_qkv A-frags
__device__ uint4 g_wpf[(size_t)32 * 32 * 32];            // 0.5MB w_proj A-frags
__device__ float2 g_gnpart[BATCH][GROUPS][GN_SPL];       // GN partial (sum, sumsq)

__device__ __forceinline__ uint32_t smem_u32(const void* p) {
    uint32_t a;
    asm("{ .reg .u64 t; cvta.to.shared.u64 t, %1; cvt.u32.u64 %0, t; }" : "=r"(a) : "l"(p));
    return a;
}
__device__ __forceinline__ uint32_t pack_bf16x2(float lo, float hi) {
    uint32_t d;
    asm("cvt.rn.bf16x2.f32 %0, %1, %2;" : "=r"(d) : "f"(hi), "f"(lo));
    return d;
}
__device__ __forceinline__ float ex2f(float x) {
    float r; asm("ex2.approx.ftz.f32 %0, %1;" : "=f"(r) : "f"(x)); return r;
}
#define MMA_BF16(d, a, b) \
    asm volatile("mma.sync.aligned.m16n8k16.row.col.f32.bf16.bf16.f32 " \
                 "{%0,%1,%2,%3}, {%4,%5,%6,%7}, {%8,%9}, {%0,%1,%2,%3};" \
                 : "+f"((d)[0]), "+f"((d)[1]), "+f"((d)[2]), "+f"((d)[3]) \
                 : "r"((a).x), "r"((a).y), "r"((a).z), "r"((a).w), \
                   "r"((b).x), "r"((b).y))

__device__ __forceinline__ void cp16(uint32_t dst, const void* src) {
    asm volatile("cp.async.cg.shared.global [%0], [%1], 16;" :: "r"(dst), "l"(src));
}
#define CP_COMMIT() asm volatile("cp.async.commit_group;" ::: "memory")
#define CP_WAIT(n)  asm volatile("cp.async.wait_group %0;" :: "n"(n) : "memory")

// ---------------- fused prep: GN partial stats (blocks 0..511) + weight packing (512..1023) ----------------
__global__ void __launch_bounds__(256) prep_kernel(const float* __restrict__ x,
                                                   const float* __restrict__ Wq,
                                                   const float* __restrict__ Wp,
                                                   uint4* __restrict__ Wqf,
                                                   uint4* __restrict__ Wpf) {
    const int bid = blockIdx.x;
    const int tid = threadIdx.x;
    if (bid < 512) {
        // --- GN stats slice: g = bid&31, b = (bid>>5)&1, z = bid>>6 ---
        const int g = bid & 31, b = (bid >> 5) & 1, z = bid >> 6;
        const size_t base = ((size_t)b * C + g * CPG) * L;
        const int QSPAN4 = (CPG * L) / (4 * GN_SPL);   // 2048
        const float4* x4 = (const float4*)(x + base) + (size_t)z * QSPAN4;
        float s = 0.f, ss = 0.f;
        #pragma unroll 4
        for (int i = tid; i < QSPAN4; i += 256) {
            float4 v = x4[i];
            s  += v.x + v.y + v.z + v.w;
            ss += v.x * v.x + v.y * v.y + v.z * v.z + v.w * v.w;
        }
        __shared__ float rs[256], rss[256];
        rs[tid] = s; rss[tid] = ss;
        __syncthreads();
        for (int off = 128; off; off >>= 1) {
            if (tid < off) { rs[tid] += rs[tid + off]; rss[tid] += rss[tid + off]; }
            __syncthreads();
        }
        if (tid == 0) g_gnpart[b][g][z] = make_float2(rs[0], rss[0]);
    } else {
        // --- weight packing: blocks 512..895 -> wq, 896..1023 -> wp ---
        const int pw = bid - 512;
        const float* W = (pw < 384) ? Wq : Wp;
        uint4* Wf = (pw < 384) ? Wqf : Wpf;
        const int idx = ((pw < 384) ? pw : (pw - 384)) * 256 + tid;
        const int blk = idx >> 5, lane = idx & 31;
        const int mt = blk >> 5, kt = blk & 31;
        const int gid = lane >> 2, tig = lane & 3;
        const float* r0 = W + (size_t)(mt * 16 + gid) * 512 + kt * 16;
        const float* r8 = r0 + 8 * 512;
        float2 a0 = *(const float2*)(r0 + 2 * tig);
        float2 a1 = *(const float2*)(r8 + 2 * tig);
        float2 a2 = *(const float2*)(r0 + 2 * tig + 8);
        float2 a3 = *(const float2*)(r8 + 2 * tig + 8);
        uint4 o;
        o.x = pack_bf16x2(a0.x, a0.y); o.y = pack_bf16x2(a1.x, a1.y);
        o.z = pack_bf16x2(a2.x, a2.y); o.w = pack_bf16x2(a3.x, a3.y);
        Wf[idx] = o;
    }
}

// ---------------- GN pass 2: normalize + emit xn B-frags (slice z) ----------------
__global__ void __launch_bounds__(256) gn_apply_kernel(const float* __restrict__ x,
                                                       const float* __restrict__ gw,
                                                       const float* __restrict__ gb,
                                                       uint2* __restrict__ Bf) {
    const int g = blockIdx.x, b = blockIdx.y, z = blockIdx.z;
    const int tid = threadIdx.x;
    const size_t base = ((size_t)b * C + g * CPG) * L;
    const float* xr = x + base;
    const int SPAN = CPG * L;

    __shared__ float ga_s[CPG], be_s[CPG];
    if (tid < CPG) {
        float s = 0.f, ss = 0.f;
        #pragma unroll
        for (int zz = 0; zz < GN_SPL; zz++) {
            float2 p = g_gnpart[b][g][zz];
            s += p.x; ss += p.y;
        }
        float mean = s / SPAN;
        float var  = ss / SPAN - mean * mean;
        float rstd = rsqrtf(var + EPS);
        float ga = gw[g * CPG + tid] * rstd;
        ga_s[tid] = ga;
        be_s[tid] = gb[g * CPG + tid] - mean * ga;
    }
    __syncthreads();

    uint2* dst = Bf + (size_t)b * 524288 + (size_t)g * 32;
    const int i0 = z * (16384 / GN_SPL);
    #pragma unroll 4
    for (int i = i0 + tid; i < i0 + 16384 / GN_SPL; i += 256) {
        const int nt = i >> 5, lane = i & 31;
        const int gid = lane >> 2, tig = lane & 3;
        const int n = nt * 8 + gid;
        const int lc = 2 * tig;
        float v0 = xr[(size_t)lc * L + n]       * ga_s[lc]     + be_s[lc];
        float v1 = xr[(size_t)(lc + 1) * L + n] * ga_s[lc + 1] + be_s[lc + 1];
        float v8 = xr[(size_t)(lc + 8) * L + n] * ga_s[lc + 8] + be_s[lc + 8];
        float v9 = xr[(size_t)(lc + 9) * L + n] * ga_s[lc + 9] + be_s[lc + 9];
        uint2 o;
        o.x = pack_bf16x2(v0, v1);
        o.y = pack_bf16x2(v8, v9);
        dst[(size_t)nt * 1024 + lane] = o;
    }
}

// ---------------- QKV GEMM: 128 threads, warp=64mx64n ----------------
#define QKV_SMEM 66560   // max(2 x 16KB staging, 128x130 fp32 T)

__global__ void __launch_bounds__(128) gemm_qkv_kernel(const uint4* __restrict__ Af,
                                                       const uint2* __restrict__ Bf,
                                                       const float* __restrict__ bias,
                                                       uint4* __restrict__ qf,
                                                       uint2* __restrict__ kf,
                                                       uint2* __restrict__ vf) {
    extern __shared__ char dynsm[];
    const uint32_t sb = smem_u32(dynsm);
    float* T = (float*)dynsm;
    const int tid = threadIdx.x, w = tid >> 5, l = tid & 31;
    const int mi2 = w >> 1, ni2 = w & 1, gid = l >> 2, tig = l & 3;
    const int nb = blockIdx.x, mb = blockIdx.y, bz = blockIdx.z;
    Bf += (size_t)bz * 524288;

    auto issue = [&](int kc, int s) {
        #pragma unroll
        for (int j = 0; j < 4; j++) {          // A: 512 x 16B
            const int e = tid + j * 128;
            const int bl = e >> 5, ln = e & 31;
            const int i = bl >> 1, ktl = bl & 1;
            cp16(sb + s * 16384 + e * 16,
                 (const char*)(Af + ((size_t)(mb * 8 + i) * 32 + kc * 2 + ktl) * 32 + ln));
        }
        #pragma unroll
        for (int j = 0; j < 4; j++) {          // B: 512 x 16B
            const int f = tid + j * 128;
            const int bl = f >> 4, lp = f & 15;
            const int nt = bl >> 1, ktl = bl & 1;
            cp16(sb + s * 16384 + 8192 + bl * 256 + lp * 16,
                 (const char*)Bf + ((size_t)(nb * 16 + nt) * 32 + kc * 2 + ktl) * 256 + lp * 16);
        }
    };

    issue(0, 0); CP_COMMIT();
    float acc[4][8][4] = {};
    for (int t = 0; t < 16; t++) {
        CP_WAIT(0);
        __syncthreads();
        if (t + 1 < 16) { issue(t + 1, (t + 1) & 1); CP_COMMIT(); }
        const int s = t & 1;
        #pragma unroll
        for (int ktl = 0; ktl < 2; ktl++) {
            uint4 A[4];
            #pragma unroll
            for (int mf = 0; mf < 4; mf++)
                A[mf] = *(const uint4*)(dynsm + s * 16384 +
                                        (((mi2 * 4 + mf) * 2 + ktl) * 32 + l) * 16);
            #pragma unroll
            for (int nt = 0; nt < 8; nt++) {
                uint2 B = *(const uint2*)(dynsm + s * 16384 + 8192 +
                                          (((ni2 * 8 + nt) * 2 + ktl) * 32 + l) * 8);
                #pragma unroll
                for (int mf = 0; mf < 4; mf++) MMA_BF16(acc[mf][nt], A[mf], B);
            }
        }
    }
    __syncthreads();   // staging dead before T overwrites it

    const int sec = mb >> 2, h = mb & 3;
    const int bh = bz * NH + h;
    // Q scale folds 1/sqrt(128) * log2(e) so attention can use raw ex2
    const float qs = (sec == 0) ? (0.08838834764831845f * 1.4426950408889634f) : 1.0f;

    #pragma unroll
    for (int mf = 0; mf < 4; mf++) {
        const int m0 = mi2 * 64 + mf * 16 + gid;
        const float b0v = bias[mb * 128 + m0], b8v = bias[mb * 128 + m0 + 8];
        #pragma unroll
        for (int nt = 0; nt < 8; nt++) {
            const int n0 = ni2 * 64 + nt * 8 + 2 * tig;
            T[m0 * 130 + n0]           = (acc[mf][nt][0] + b0v) * qs;
            T[m0 * 130 + n0 + 1]       = (acc[mf][nt][1] + b0v) * qs;
            T[(m0 + 8) * 130 + n0]     = (acc[mf][nt][2] + b8v) * qs;
            T[(m0 + 8) * 130 + n0 + 1] = (acc[mf][nt][3] + b8v) * qs;
        }
    }
    __syncthreads();

    if (sec == 0) {
        uint4* dst = qf + ((size_t)bh * 32 + nb) * 2048;
        #pragma unroll
        for (int it = 0; it < 16; it++) {
            const int idx = tid + it * 128;
            const int blk = idx >> 5, ln = idx & 31;
            const int mtb = blk >> 3, ktc = blk & 7;
            const int g2 = ln >> 2, t2 = ln & 3;
            const int q = mtb * 16 + g2, c = ktc * 16 + 2 * t2;
            uint4 o;
            o.x = pack_bf16x2(T[c * 130 + q],           T[(c + 1) * 130 + q]);
            o.y = pack_bf16x2(T[c * 130 + q + 8],       T[(c + 1) * 130 + q + 8]);
            o.z = pack_bf16x2(T[(c + 8) * 130 + q],     T[(c + 9) * 130 + q]);
            o.w = pack_bf16x2(T[(c + 8) * 130 + q + 8], T[(c + 9) * 130 + q + 8]);
            dst[idx] = o;
        }
    } else if (sec == 1) {
        uint2* dst = kf + (size_t)bh * 131072 + (size_t)nb * 4096;
        #pragma unroll
        for (int it = 0; it < 32; it++) {
            const int idx = tid + it * 128;
            const int blk = idx >> 5, ln = idx & 31;
            const int ktc = blk >> 4, ntb = blk & 15;
            const int g2 = ln >> 2, t2 = ln & 3;
            const int key = ntb * 8 + g2, c0 = ktc * 16 + 2 * t2;
            uint2 o;
            o.x = pack_bf16x2(T[c0 * 130 + key],       T[(c0 + 1) * 130 + key]);
            o.y = pack_bf16x2(T[(c0 + 8) * 130 + key], T[(c0 + 9) * 130 + key]);
            dst[idx] = o;
        }
    } else {
        uint2* dst = vf + (size_t)bh * 131072 + (size_t)nb * 4096;
        #pragma unroll
        for (int it = 0; it < 32; it++) {
            const int idx = tid + it * 128;
            const int blk = idx >> 5, ln = idx & 31;
            const int ktk = blk >> 4, ntb = blk & 15;
            const int g2 = ln >> 2, t2 = ln & 3;
            const int hd = ntb * 8 + g2, key0 = ktk * 16 + 2 * t2;
            uint2 o;
            o.x = pack_bf16x2(T[hd * 130 + key0],     T[hd * 130 + key0 + 1]);
            o.y = pack_bf16x2(T[hd * 130 + key0 + 8], T[hd * 130 + key0 + 9]);
            dst[idx] = o;
        }
    }
}

// ---------------- proj GEMM: 128 threads, warp=64mx64n ----------------
#define PROJ_SMEM 32768

__global__ void __launch_bounds__(128) gemm_bf16_kernel(const uint4* __restrict__ Af,
                                                        const uint2* __restrict__ Bf,
                                                        const float* __restrict__ bias,
                                                        const float* __restrict__ resid,
                                                        float* __restrict__ out, int M) {
    extern __shared__ char psm[];
    const uint32_t sb = smem_u32(psm);
    const int tid = threadIdx.x, w = tid >> 5, l = tid & 31;
    const int mi2 = w >> 1, ni2 = w & 1, gid = l >> 2, tig = l & 3;
    const int nb = blockIdx.x, mb = blockIdx.y, bz = blockIdx.z;
    Bf += (size_t)bz * 524288;
    out += (size_t)bz * M * L;
    if (resid) resid += (size_t)bz * M * L;

    auto issue = [&](int kc, int s) {
        #pragma unroll
        for (int j = 0; j < 4; j++) {
            const int e = tid + j * 128;
            const int bl = e >> 5, ln = e & 31;
            const int i = bl >> 1, ktl = bl & 1;
            cp16(sb + s * 16384 + e * 16,
                 (const char*)(Af + ((size_t)(mb * 8 + i) * 32 + kc * 2 + ktl) * 32 + ln));
        }
        #pragma unroll
        for (int j = 0; j < 4; j++) {
            const int f = tid + j * 128;
            const int bl = f >> 4, lp = f & 15;
            const int nt = bl >> 1, ktl = bl & 1;
            cp16(sb + s * 16384 + 8192 + bl * 256 + lp * 16,
                 (const char*)Bf + ((size_t)(nb * 16 + nt) * 32 + kc * 2 + ktl) * 256 + lp * 16);
        }
    };

    issue(0, 0); CP_COMMIT();
    float acc[4][8][4] = {};
    for (int t = 0; t < 16; t++) {
        CP_WAIT(0);
        __syncthreads();
        if (t + 1 < 16) { issue(t + 1, (t + 1) & 1); CP_COMMIT(); }
        const int s = t & 1;
        #pragma unroll
        for (int ktl = 0; ktl < 2; ktl++) {
            uint4 A[4];
            #pragma unroll
            for (int mf = 0; mf < 4; mf++)
                A[mf] = *(const uint4*)(psm + s * 16384 +
                                        (((mi2 * 4 + mf) * 2 + ktl) * 32 + l) * 16);
            #pragma unroll
            for (int nt = 0; nt < 8; nt++) {
                uint2 B = *(const uint2*)(psm + s * 16384 + 8192 +
                                          (((ni2 * 8 + nt) * 2 + ktl) * 32 + l) * 8);
                #pragma unroll
                for (int mf = 0; mf < 4; mf++) MMA_BF16(acc[mf][nt], A[mf], B);
            }
        }
    }

    #pragma unroll
    for (int mf = 0; mf < 4; mf++) {
        const int m0 = mb * 128 + mi2 * 64 + mf * 16 + gid;
        const float b0v = bias[m0], b8v = bias[m0 + 8];
        #pragma unroll
        for (int nt = 0; nt < 8; nt++) {
            const int n0 = nb * 128 + ni2 * 64 + nt * 8 + 2 * tig;
            const size_t o0 = (size_t)m0 * L + n0, o8 = (size_t)(m0 + 8) * L + n0;
            float2 v0 = make_float2(acc[mf][nt][0] + b0v, acc[mf][nt][1] + b0v);
            float2 v8 = make_float2(acc[mf][nt][2] + b8v, acc[mf][nt][3] + b8v);
            if (resid) {
                float2 r0 = *(const float2*)(resid + o0);
                float2 r8 = *(const float2*)(resid + o8);
                v0.x += r0.x; v0.y += r0.y; v8.x += r8.x; v8.y += r8.y;
            }
            *(float2*)(out + o0) = v0;
            *(float2*)(out + o8) = v8;
        }
    }
}

// ---------------- attention (R7 structure, ex2 softmax) ----------------
#define SM_K0 32768
#define SM_V0 98304
#define ATT_SMEM 163840

__global__ void __launch_bounds__(256) attn_bf16_kernel(const uint4* __restrict__ qf,
                                                        const uint2* __restrict__ kf,
                                                        const uint2* __restrict__ vf,
                                                        uint2* __restrict__ attf) {
    extern __shared__ char sm[];
    const uint32_t sb = smem_u32(sm);
    __shared__ float lsum_s[2][128];

    const int tid = threadIdx.x, w = tid >> 5, l = tid & 31;
    const int qi = w >> 1, kh = w & 1;
    const int gid = l >> 2, tig = l & 3;
    const int qb = blockIdx.x, bh = blockIdx.y;
    const int b = bh >> 2, h = bh & 3;

    const char* qsrc = (const char*)(qf + ((size_t)bh * 32 + qb) * 2048);
    const char* ksrc = (const char*)(kf + (size_t)bh * 131072);
    const char* vsrc = (const char*)(vf + (size_t)bh * 131072);

    #pragma unroll
    for (int j = 0; j < 8; j++) {
        const int i = tid + j * 256;
        cp16(sb + i * 16, qsrc + i * 16);
        cp16(sb + SM_K0 + i * 16, ksrc + i * 16);
        cp16(sb + SM_V0 + i * 16, vsrc + i * 16);
    }
    CP_COMMIT();

    float oacc[2][16][4] = {};
    float lsum[2][2] = {};

    for (int t = 0; t < 32; t++) {
        CP_WAIT(0);
        __syncthreads();
        if (t + 1 < 32) {
            const int pb = (t + 1) & 1;
            const char* kp = ksrc + (size_t)(t + 1) * 32768;
            const char* vp = vsrc + (size_t)(t + 1) * 32768;
            #pragma unroll
            for (int j = 0; j < 8; j++) {
                const int i = tid + j * 256;
                cp16(sb + SM_K0 + pb * 32768 + i * 16, kp + i * 16);
                cp16(sb + SM_V0 + pb * 32768 + i * 16, vp + i * 16);
            }
            CP_COMMIT();
        }

        const uint32_t Kb = SM_K0 + (t & 1) * 32768;
        float sacc[2][8][4] = {};
        #pragma unroll
        for (int ktc = 0; ktc < 8; ktc++) {
            uint4 A0 = *(const uint4*)(sm + (((qi * 2 + 0) * 8 + ktc) * 32 + l) * 16);
            uint4 A1 = *(const uint4*)(sm + (((qi * 2 + 1) * 8 + ktc) * 32 + l) * 16);
            #pragma unroll
            for (int nt = 0; nt < 8; nt++) {
                uint2 B = *(const uint2*)(sm + Kb + ((ktc * 16 + kh * 8 + nt) * 32 + l) * 8);
                MMA_BF16(sacc[0][nt], A0, B);
                MMA_BF16(sacc[1][nt], A1, B);
            }
        }

        uint4 pP[2][4];
        #pragma unroll
        for (int mt = 0; mt < 2; mt++) {
            #pragma unroll
            for (int kc = 0; kc < 4; kc++) {
                const int nt0 = 2 * kc, nt1 = 2 * kc + 1;
                float p00 = ex2f(sacc[mt][nt0][0]), p01 = ex2f(sacc[mt][nt0][1]);
                float p02 = ex2f(sacc[mt][nt0][2]), p03 = ex2f(sacc[mt][nt0][3]);
                float p10 = ex2f(sacc[mt][nt1][0]), p11 = ex2f(sacc[mt][nt1][1]);
                float p12 = ex2f(sacc[mt][nt1][2]), p13 = ex2f(sacc[mt][nt1][3]);
                lsum[mt][0] += p00 + p01 + p10 + p11;
                lsum[mt][1] += p02 + p03 + p12 + p13;
                pP[mt][kc].x = pack_bf16x2(p00, p01);
                pP[mt][kc].y = pack_bf16x2(p02, p03);
                pP[mt][kc].z = pack_bf16x2(p10, p11);
                pP[mt][kc].w = pack_bf16x2(p12, p13);
            }
        }

        const uint32_t Vb = SM_V0 + (t & 1) * 32768;
        #pragma unroll
        for (int kt = 0; kt < 4; kt++) {
            const uint4 A0 = pP[0][kt], A1 = pP[1][kt];
            #pragma unroll
            for (int nt = 0; nt < 16; nt++) {
                uint2 B = *(const uint2*)(sm + Vb + (((kh * 4 + kt) * 16 + nt) * 32 + l) * 8);
                MMA_BF16(oacc[0][nt], A0, B);
                MMA_BF16(oacc[1][nt], A1, B);
            }
        }
    }

    #pragma unroll
    for (int mt = 0; mt < 2; mt++)
        #pragma unroll
        for (int dr = 0; dr < 2; dr++) {
            float v = lsum[mt][dr];
            v += __shfl_xor_sync(0xffffffffu, v, 1);
            v += __shfl_xor_sync(0xffffffffu, v, 2);
            lsum[mt][dr] = v;
        }
    __syncthreads();
    float* Ob = (float*)sm;
    if (tig == 0) {
        #pragma unroll
        for (int mt = 0; mt < 2; mt++)
            #pragma unroll
            for (int dr = 0; dr < 2; dr++)
                lsum_s[kh][qi * 32 + mt * 16 + gid + 8 * dr] = lsum[mt][dr];
    }
    if (kh == 0) {
        #pragma unroll
        for (int mt = 0; mt < 2; mt++)
            #pragma unroll
            for (int nt = 0; nt < 16; nt++)
                #pragma unroll
                for (int j = 0; j < 4; j++) {
                    const int q  = qi * 32 + mt * 16 + gid + 8 * (j >> 1);
                    const int hd = nt * 8 + tig * 2 + (j & 1);
                    Ob[hd * 132 + q] = oacc[mt][nt][j];
                }
    }
    __syncthreads();
    if (kh == 1) {
        #pragma unroll
        for (int mt = 0; mt < 2; mt++)
            #pragma unroll
            for (int nt = 0; nt < 16; nt++)
                #pragma unroll
                for (int j = 0; j < 4; j++) {
                    const int q  = qi * 32 + mt * 16 + gid + 8 * (j >> 1);
                    const int hd = nt * 8 + tig * 2 + (j & 1);
                    Ob[hd * 132 + q] += oacc[mt][nt][j];
                }
    }
    __syncthreads();

    const size_t attbase = (size_t)b * 524288;
    #pragma unroll
    for (int it = 0; it < 16; it++) {
        const int slot = tid + it * 256;
        const int lb = slot >> 5, ln = slot & 31;
        const int ntl = lb >> 3, ktl = lb & 7;
        const int g2 = ln >> 2, t2 = ln & 3;
        const int cl = ktl * 16 + 2 * t2;
        const int ql = ntl * 8 + g2;
        const float linv = 1.0f / (lsum_s[0][ql] + lsum_s[1][ql]);
        uint2 o;
        o.x = pack_bf16x2(Ob[cl * 132 + ql] * linv,       Ob[(cl + 1) * 132 + ql] * linv);
        o.y = pack_bf16x2(Ob[(cl + 8) * 132 + ql] * linv, Ob[(cl + 9) * 132 + ql] * linv);
        attf[attbase + ((size_t)(qb * 16 + ntl) * 32 + (h * 8 + ktl)) * 32 + ln] = o;
    }
}

// ---------------- host ----------------
extern "C" void kernel_launch(void* const* d_in, const int* in_sizes, int n_in,
                              void* d_out, int out_size) {
    const float* x      = (const float*)d_in[0];
    const float* gn_w   = (const float*)d_in[1];
    const float* gn_b   = (const float*)d_in[2];
    const float* w_qkv  = (const float*)d_in[3];
    const float* b_qkv  = (const float*)d_in[4];
    const float* w_proj = (const float*)d_in[5];
    const float* b_proj = (const float*)d_in[6];
    float* out = (float*)d_out;

    uint4 *qf_p, *wqf_p, *wpf_p;
    uint2 *kf_p, *vf_p, *xnf_p, *attf_p;
    cudaGetSymbolAddress((void**)&qf_p, g_qf);
    cudaGetSymbolAddress((void**)&kf_p, g_kf);
    cudaGetSymbolAddress((void**)&vf_p, g_vf);
    cudaGetSymbolAddress((void**)&xnf_p, g_xnf);
    cudaGetSymbolAddress((void**)&attf_p, g_attf);
    cudaGetSymbolAddress((void**)&wqf_p, g_wqf);
    cudaGetSymbolAddress((void**)&wpf_p, g_wpf);

    // 1) fused prep (GN stats + weight packing), then GN apply/pack
    prep_kernel<<<1024, 256>>>(x, w_qkv, w_proj, wqf_p, wpf_p);
    gn_apply_kernel<<<dim3(GROUPS, BATCH, GN_SPL), 256>>>(x, gn_w, gn_b, xnf_p);

    // 2) QKV GEMM (128 threads, 64x64 warps) with fused q/k/v fragment epilogue
    cudaFuncSetAttribute(gemm_qkv_kernel, cudaFuncAttributeMaxDynamicSharedMemorySize, QKV_SMEM);
    gemm_qkv_kernel<<<dim3(32, 12, BATCH), 128, QKV_SMEM>>>(wqf_p, xnf_p, b_qkv,
                                                            qf_p, kf_p, vf_p);

    // 3) attention (128-key tiles, register P), emits proj B-frags
    cudaFuncSetAttribute(attn_bf16_kernel, cudaFuncAttributeMaxDynamicSharedMemorySize, ATT_SMEM);
    attn_bf16_kernel<<<dim3(L / 128, BATCH * NH), 256, ATT_SMEM>>>(qf_p, kf_p, vf_p, attf_p);

    // 4) proj GEMM (128 threads, 64x64 warps) + bias + residual -> out
    cudaFuncSetAttribute(gemm_bf16_kernel, cudaFuncAttributeMaxDynamicSharedMemorySize, PROJ_SMEM);
    gemm_bf16_kernel<<<dim3(32, 4, BATCH), 128, PROJ_SMEM>>>(wpf_p, attf_p, b_proj, x, out, C);
}

// round 15
// speedup vs baseline: 1.1031x; 1.0011x over previous
#include <cuda_runtime.h>
#include <math.h>
#include <stdint.h>

#define BATCH 2
#define C 512
#define L 4096
#define NH 4
#define HD 128
#define GROUPS 32
#define CPG (C / GROUPS)   // 16
#define EPS 1e-5f
#define GN_SPL 8

// ---------------- scratch (static device globals; no allocation) ----------------
__device__ uint4 g_qf[(size_t)BATCH * NH * 32 * 2048];   // 8 MB  Q A-frags
__device__ uint2 g_kf[(size_t)BATCH * NH * 32 * 4096];   // 8 MB  K B-frags
__device__ uint2 g_vf[(size_t)BATCH * NH * 32 * 4096];   // 8 MB  V B-frags
__device__ uint2 g_xnf[(size_t)BATCH * 512 * 32 * 32];   // 8 MB  xn B-frags
__device__ uint2 g_attf[(size_t)BATCH * 512 * 32 * 32];  // 8 MB  att B-frags
__device__ uint4 g_wqf[(size_t)96 * 32 * 32];            // 1.5MB w_qkv A-frags
__device__ uint4 g_wpf[(size_t)32 * 32 * 32];            // 0.5MB w_proj A-frags
__device__ float2 g_gnpart[BATCH][GROUPS][GN_SPL];       // GN partial (sum, sumsq)

__device__ __forceinline__ uint32_t smem_u32(const void* p) {
    uint32_t a;
    asm("{ .reg .u64 t; cvta.to.shared.u64 t, %1; cvt.u32.u64 %0, t; }" : "=r"(a) : "l"(p));
    return a;
}
__device__ __forceinline__ uint32_t pack_bf16x2(float lo, float hi) {
    uint32_t d;
    asm("cvt.rn.bf16x2.f32 %0, %1, %2;" : "=r"(d) : "f"(hi), "f"(lo));
    return d;
}
__device__ __forceinline__ uint32_t ex2_bf16x2(uint32_t x) {
    uint32_t d;
    asm("ex2.approx.ftz.bf16x2 %0, %1;" : "=r"(d) : "r"(x));
    return d;
}
#define MMA_BF16(d, a, b) \
    asm volatile("mma.sync.aligned.m16n8k16.row.col.f32.bf16.bf16.f32 " \
                 "{%0,%1,%2,%3}, {%4,%5,%6,%7}, {%8,%9}, {%0,%1,%2,%3};" \
                 : "+f"((d)[0]), "+f"((d)[1]), "+f"((d)[2]), "+f"((d)[3]) \
                 : "r"((a).x), "r"((a).y), "r"((a).z), "r"((a).w), \
                   "r"((b).x), "r"((b).y))

__device__ __forceinline__ void cp16(uint32_t dst, const void* src) {
    asm volatile("cp.async.cg.shared.global [%0], [%1], 16;" :: "r"(dst), "l"(src));
}
#define CP_COMMIT() asm volatile("cp.async.commit_group;" ::: "memory")
#define CP_WAIT(n)  asm volatile("cp.async.wait_group %0;" :: "n"(n) : "memory")

// ---------------- fused prep: GN partial stats (blocks 0..511) + weight packing (512..1023) ----------------
__global__ void __launch_bounds__(256) prep_kernel(const float* __restrict__ x,
                                                   const float* __restrict__ Wq,
                                                   const float* __restrict__ Wp,
                                                   uint4* __restrict__ Wqf,
                                                   uint4* __restrict__ Wpf) {
    const int bid = blockIdx.x;
    const int tid = threadIdx.x;
    if (bid < 512) {
        const int g = bid & 31, b = (bid >> 5) & 1, z = bid >> 6;
        const size_t base = ((size_t)b * C + g * CPG) * L;
        const int QSPAN4 = (CPG * L) / (4 * GN_SPL);   // 2048
        const float4* x4 = (const float4*)(x + base) + (size_t)z * QSPAN4;
        float s = 0.f, ss = 0.f;
        #pragma unroll 4
        for (int i = tid; i < QSPAN4; i += 256) {
            float4 v = x4[i];
            s  += v.x + v.y + v.z + v.w;
            ss += v.x * v.x + v.y * v.y + v.z * v.z + v.w * v.w;
        }
        __shared__ float rs[256], rss[256];
        rs[tid] = s; rss[tid] = ss;
        __syncthreads();
        for (int off = 128; off; off >>= 1) {
            if (tid < off) { rs[tid] += rs[tid + off]; rss[tid] += rss[tid + off]; }
            __syncthreads();
        }
        if (tid == 0) g_gnpart[b][g][z] = make_float2(rs[0], rss[0]);
    } else {
        const int pw = bid - 512;
        const float* W = (pw < 384) ? Wq : Wp;
        uint4* Wf = (pw < 384) ? Wqf : Wpf;
        const int idx = ((pw < 384) ? pw : (pw - 384)) * 256 + tid;
        const int blk = idx >> 5, lane = idx & 31;
        const int mt = blk >> 5, kt = blk & 31;
        const int gid = lane >> 2, tig = lane & 3;
        const float* r0 = W + (size_t)(mt * 16 + gid) * 512 + kt * 16;
        const float* r8 = r0 + 8 * 512;
        float2 a0 = *(const float2*)(r0 + 2 * tig);
        float2 a1 = *(const float2*)(r8 + 2 * tig);
        float2 a2 = *(const float2*)(r0 + 2 * tig + 8);
        float2 a3 = *(const float2*)(r8 + 2 * tig + 8);
        uint4 o;
        o.x = pack_bf16x2(a0.x, a0.y); o.y = pack_bf16x2(a1.x, a1.y);
        o.z = pack_bf16x2(a2.x, a2.y); o.w = pack_bf16x2(a3.x, a3.y);
        Wf[idx] = o;
    }
}

// ---------------- GN pass 2: normalize + emit xn B-frags (slice z) ----------------
__global__ void __launch_bounds__(256) gn_apply_kernel(const float* __restrict__ x,
                                                       const float* __restrict__ gw,
                                                       const float* __restrict__ gb,
                                                       uint2* __restrict__ Bf) {
    const int g = blockIdx.x, b = blockIdx.y, z = blockIdx.z;
    const int tid = threadIdx.x;
    const size_t base = ((size_t)b * C + g * CPG) * L;
    const float* xr = x + base;
    const int SPAN = CPG * L;

    __shared__ float ga_s[CPG], be_s[CPG];
    if (tid < CPG) {
        float s = 0.f, ss = 0.f;
        #pragma unroll
        for (int zz = 0; zz < GN_SPL; zz++) {
            float2 p = g_gnpart[b][g][zz];
            s += p.x; ss += p.y;
        }
        float mean = s / SPAN;
        float var  = ss / SPAN - mean * mean;
        float rstd = rsqrtf(var + EPS);
        float ga = gw[g * CPG + tid] * rstd;
        ga_s[tid] = ga;
        be_s[tid] = gb[g * CPG + tid] - mean * ga;
    }
    __syncthreads();

    uint2* dst = Bf + (size_t)b * 524288 + (size_t)g * 32;
    const int i0 = z * (16384 / GN_SPL);
    #pragma unroll 4
    for (int i = i0 + tid; i < i0 + 16384 / GN_SPL; i += 256) {
        const int nt = i >> 5, lane = i & 31;
        const int gid = lane >> 2, tig = lane & 3;
        const int n = nt * 8 + gid;
        const int lc = 2 * tig;
        float v0 = xr[(size_t)lc * L + n]       * ga_s[lc]     + be_s[lc];
        float v1 = xr[(size_t)(lc + 1) * L + n] * ga_s[lc + 1] + be_s[lc + 1];
        float v8 = xr[(size_t)(lc + 8) * L + n] * ga_s[lc + 8] + be_s[lc + 8];
        float v9 = xr[(size_t)(lc + 9) * L + n] * ga_s[lc + 9] + be_s[lc + 9];
        uint2 o;
        o.x = pack_bf16x2(v0, v1);
        o.y = pack_bf16x2(v8, v9);
        dst[(size_t)nt * 1024 + lane] = o;
    }
}

// ---------------- QKV GEMM: 128 threads, warp=64mx64n ----------------
#define QKV_SMEM 66560   // max(2 x 16KB staging, 128x130 fp32 T)

__global__ void __launch_bounds__(128) gemm_qkv_kernel(const uint4* __restrict__ Af,
                                                       const uint2* __restrict__ Bf,
                                                       const float* __restrict__ bias,
                                                       uint4* __restrict__ qf,
                                                       uint2* __restrict__ kf,
                                                       uint2* __restrict__ vf) {
    extern __shared__ char dynsm[];
    const uint32_t sb = smem_u32(dynsm);
    float* T = (float*)dynsm;
    const int tid = threadIdx.x, w = tid >> 5, l = tid & 31;
    const int mi2 = w >> 1, ni2 = w & 1, gid = l >> 2, tig = l & 3;
    const int nb = blockIdx.x, mb = blockIdx.y, bz = blockIdx.z;
    Bf += (size_t)bz * 524288;

    auto issue = [&](int kc, int s) {
        #pragma unroll
        for (int j = 0; j < 4; j++) {          // A: 512 x 16B
            const int e = tid + j * 128;
            const int bl = e >> 5, ln = e & 31;
            const int i = bl >> 1, ktl = bl & 1;
            cp16(sb + s * 16384 + e * 16,
                 (const char*)(Af + ((size_t)(mb * 8 + i) * 32 + kc * 2 + ktl) * 32 + ln));
        }
        #pragma unroll
        for (int j = 0; j < 4; j++) {          // B: 512 x 16B
            const int f = tid + j * 128;
            const int bl = f >> 4, lp = f & 15;
            const int nt = bl >> 1, ktl = bl & 1;
            cp16(sb + s * 16384 + 8192 + bl * 256 + lp * 16,
                 (const char*)Bf + ((size_t)(nb * 16 + nt) * 32 + kc * 2 + ktl) * 256 + lp * 16);
        }
    };

    issue(0, 0); CP_COMMIT();
    float acc[4][8][4] = {};
    for (int t = 0; t < 16; t++) {
        CP_WAIT(0);
        __syncthreads();
        if (t + 1 < 16) { issue(t + 1, (t + 1) & 1); CP_COMMIT(); }
        const int s = t & 1;
        #pragma unroll
        for (int ktl = 0; ktl < 2; ktl++) {
            uint4 A[4];
            #pragma unroll
            for (int mf = 0; mf < 4; mf++)
                A[mf] = *(const uint4*)(dynsm + s * 16384 +
                                        (((mi2 * 4 + mf) * 2 + ktl) * 32 + l) * 16);
            #pragma unroll
            for (int nt = 0; nt < 8; nt++) {
                uint2 B = *(const uint2*)(dynsm + s * 16384 + 8192 +
                                          (((ni2 * 8 + nt) * 2 + ktl) * 32 + l) * 8);
                #pragma unroll
                for (int mf = 0; mf < 4; mf++) MMA_BF16(acc[mf][nt], A[mf], B);
            }
        }
    }
    __syncthreads();   // staging dead before T overwrites it

    const int sec = mb >> 2, h = mb & 3;
    const int bh = bz * NH + h;
    // Q scale folds 1/sqrt(128) * log2(e) so attention can use raw ex2
    const float qs = (sec == 0) ? (0.08838834764831845f * 1.4426950408889634f) : 1.0f;

    #pragma unroll
    for (int mf = 0; mf < 4; mf++) {
        const int m0 = mi2 * 64 + mf * 16 + gid;
        const float b0v = bias[mb * 128 + m0], b8v = bias[mb * 128 + m0 + 8];
        #pragma unroll
        for (int nt = 0; nt < 8; nt++) {
            const int n0 = ni2 * 64 + nt * 8 + 2 * tig;
            T[m0 * 130 + n0]           = (acc[mf][nt][0] + b0v) * qs;
            T[m0 * 130 + n0 + 1]       = (acc[mf][nt][1] + b0v) * qs;
            T[(m0 + 8) * 130 + n0]     = (acc[mf][nt][2] + b8v) * qs;
            T[(m0 + 8) * 130 + n0 + 1] = (acc[mf][nt][3] + b8v) * qs;
        }
    }
    __syncthreads();

    if (sec == 0) {
        uint4* dst = qf + ((size_t)bh * 32 + nb) * 2048;
        #pragma unroll
        for (int it = 0; it < 16; it++) {
            const int idx = tid + it * 128;
            const int blk = idx >> 5, ln = idx & 31;
            const int mtb = blk >> 3, ktc = blk & 7;
            const int g2 = ln >> 2, t2 = ln & 3;
            const int q = mtb * 16 + g2, c = ktc * 16 + 2 * t2;
            uint4 o;
            o.x = pack_bf16x2(T[c * 130 + q],           T[(c + 1) * 130 + q]);
            o.y = pack_bf16x2(T[c * 130 + q + 8],       T[(c + 1) * 130 + q + 8]);
            o.z = pack_bf16x2(T[(c + 8) * 130 + q],     T[(c + 9) * 130 + q]);
            o.w = pack_bf16x2(T[(c + 8) * 130 + q + 8], T[(c + 9) * 130 + q + 8]);
            dst[idx] = o;
        }
    } else if (sec == 1) {
        uint2* dst = kf + (size_t)bh * 131072 + (size_t)nb * 4096;
        #pragma unroll
        for (int it = 0; it < 32; it++) {
            const int idx = tid + it * 128;
            const int blk = idx >> 5, ln = idx & 31;
            const int ktc = blk >> 4, ntb = blk & 15;
            const int g2 = ln >> 2, t2 = ln & 3;
            const int key = ntb * 8 + g2, c0 = ktc * 16 + 2 * t2;
            uint2 o;
            o.x = pack_bf16x2(T[c0 * 130 + key],       T[(c0 + 1) * 130 + key]);
            o.y = pack_bf16x2(T[(c0 + 8) * 130 + key], T[(c0 + 9) * 130 + key]);
            dst[idx] = o;
        }
    } else {
        uint2* dst = vf + (size_t)bh * 131072 + (size_t)nb * 4096;
        #pragma unroll
        for (int it = 0; it < 32; it++) {
            const int idx = tid + it * 128;
            const int blk = idx >> 5, ln = idx & 31;
            const int ktk = blk >> 4, ntb = blk & 15;
            const int g2 = ln >> 2, t2 = ln & 3;
            const int hd = ntb * 8 + g2, key0 = ktk * 16 + 2 * t2;
            uint2 o;
            o.x = pack_bf16x2(T[hd * 130 + key0],     T[hd * 130 + key0 + 1]);
            o.y = pack_bf16x2(T[hd * 130 + key0 + 8], T[hd * 130 + key0 + 9]);
            dst[idx] = o;
        }
    }
}

// ---------------- proj GEMM: 128 threads, warp=64mx64n ----------------
#define PROJ_SMEM 32768

__global__ void __launch_bounds__(128) gemm_bf16_kernel(const uint4* __restrict__ Af,
                                                        const uint2* __restrict__ Bf,
                                                        const float* __restrict__ bias,
                                                        const float* __restrict__ resid,
                                                        float* __restrict__ out, int M) {
    extern __shared__ char psm[];
    const uint32_t sb = smem_u32(psm);
    const int tid = threadIdx.x, w = tid >> 5, l = tid & 31;
    const int mi2 = w >> 1, ni2 = w & 1, gid = l >> 2, tig = l & 3;
    const int nb = blockIdx.x, mb = blockIdx.y, bz = blockIdx.z;
    Bf += (size_t)bz * 524288;
    out += (size_t)bz * M * L;
    if (resid) resid += (size_t)bz * M * L;

    auto issue = [&](int kc, int s) {
        #pragma unroll
        for (int j = 0; j < 4; j++) {
            const int e = tid + j * 128;
            const int bl = e >> 5, ln = e & 31;
            const int i = bl >> 1, ktl = bl & 1;
            cp16(sb + s * 16384 + e * 16,
                 (const char*)(Af + ((size_t)(mb * 8 + i) * 32 + kc * 2 + ktl) * 32 + ln));
        }
        #pragma unroll
        for (int j = 0; j < 4; j++) {
            const int f = tid + j * 128;
            const int bl = f >> 4, lp = f & 15;
            const int nt = bl >> 1, ktl = bl & 1;
            cp16(sb + s * 16384 + 8192 + bl * 256 + lp * 16,
                 (const char*)Bf + ((size_t)(nb * 16 + nt) * 32 + kc * 2 + ktl) * 256 + lp * 16);
        }
    };

    issue(0, 0); CP_COMMIT();
    float acc[4][8][4] = {};
    for (int t = 0; t < 16; t++) {
        CP_WAIT(0);
        __syncthreads();
        if (t + 1 < 16) { issue(t + 1, (t + 1) & 1); CP_COMMIT(); }
        const int s = t & 1;
        #pragma unroll
        for (int ktl = 0; ktl < 2; ktl++) {
            uint4 A[4];
            #pragma unroll
            for (int mf = 0; mf < 4; mf++)
                A[mf] = *(const uint4*)(psm + s * 16384 +
                                        (((mi2 * 4 + mf) * 2 + ktl) * 32 + l) * 16);
            #pragma unroll
            for (int nt = 0; nt < 8; nt++) {
                uint2 B = *(const uint2*)(psm + s * 16384 + 8192 +
                                          (((ni2 * 8 + nt) * 2 + ktl) * 32 + l) * 8);
                #pragma unroll
                for (int mf = 0; mf < 4; mf++) MMA_BF16(acc[mf][nt], A[mf], B);
            }
        }
    }

    #pragma unroll
    for (int mf = 0; mf < 4; mf++) {
        const int m0 = mb * 128 + mi2 * 64 + mf * 16 + gid;
        const float b0v = bias[m0], b8v = bias[m0 + 8];
        #pragma unroll
        for (int nt = 0; nt < 8; nt++) {
            const int n0 = nb * 128 + ni2 * 64 + nt * 8 + 2 * tig;
            const size_t o0 = (size_t)m0 * L + n0, o8 = (size_t)(m0 + 8) * L + n0;
            float2 v0 = make_float2(acc[mf][nt][0] + b0v, acc[mf][nt][1] + b0v);
            float2 v8 = make_float2(acc[mf][nt][2] + b8v, acc[mf][nt][3] + b8v);
            if (resid) {
                float2 r0 = *(const float2*)(resid + o0);
                float2 r8 = *(const float2*)(resid + o8);
                v0.x += r0.x; v0.y += r0.y; v8.x += r8.x; v8.y += r8.y;
            }
            *(float2*)(out + o0) = v0;
            *(float2*)(out + o8) = v8;
        }
    }
}

// ---------------- attention: bf16x2 exp + tensor-pipe lsum ----------------
#define SM_K0 32768
#define SM_V0 98304
#define ATT_SMEM 163840

__global__ void __launch_bounds__(256) attn_bf16_kernel(const uint4* __restrict__ qf,
                                                        const uint2* __restrict__ kf,
                                                        const uint2* __restrict__ vf,
                                                        uint2* __restrict__ attf) {
    extern __shared__ char sm[];
    const uint32_t sb = smem_u32(sm);
    __shared__ float lsum_s[2][128];

    const int tid = threadIdx.x, w = tid >> 5, l = tid & 31;
    const int qi = w >> 1, kh = w & 1;
    const int gid = l >> 2, tig = l & 3;
    const int qb = blockIdx.x, bh = blockIdx.y;
    const int b = bh >> 2, h = bh & 3;

    const char* qsrc = (const char*)(qf + ((size_t)bh * 32 + qb) * 2048);
    const char* ksrc = (const char*)(kf + (size_t)bh * 131072);
    const char* vsrc = (const char*)(vf + (size_t)bh * 131072);

    #pragma unroll
    for (int j = 0; j < 8; j++) {
        const int i = tid + j * 256;
        cp16(sb + i * 16, qsrc + i * 16);
        cp16(sb + SM_K0 + i * 16, ksrc + i * 16);
        cp16(sb + SM_V0 + i * 16, vsrc + i * 16);
    }
    CP_COMMIT();

    // ones B-frag (bf16 1.0 in column n=0 only): row-sum MMA operand
    uint2 Bones;
    Bones.x = (gid == 0) ? pack_bf16x2(1.0f, 1.0f) : 0u;
    Bones.y = Bones.x;

    float oacc[2][16][4] = {};
    float lacc[2][4] = {};   // col 0 (and col-pair 2) accumulate row sums of P

    for (int t = 0; t < 32; t++) {
        CP_WAIT(0);
        __syncthreads();
        if (t + 1 < 32) {
            const int pb = (t + 1) & 1;
            const char* kp = ksrc + (size_t)(t + 1) * 32768;
            const char* vp = vsrc + (size_t)(t + 1) * 32768;
            #pragma unroll
            for (int j = 0; j < 8; j++) {
                const int i = tid + j * 256;
                cp16(sb + SM_K0 + pb * 32768 + i * 16, kp + i * 16);
                cp16(sb + SM_V0 + pb * 32768 + i * 16, vp + i * 16);
            }
            CP_COMMIT();
        }

        const uint32_t Kb = SM_K0 + (t & 1) * 32768;
        // ---- S = Q K^T (warp: 32q x its 64-key half) ----
        float sacc[2][8][4] = {};
        #pragma unroll
        for (int ktc = 0; ktc < 8; ktc++) {
            uint4 A0 = *(const uint4*)(sm + (((qi * 2 + 0) * 8 + ktc) * 32 + l) * 16);
            uint4 A1 = *(const uint4*)(sm + (((qi * 2 + 1) * 8 + ktc) * 32 + l) * 16);
            #pragma unroll
            for (int nt = 0; nt < 8; nt++) {
                uint2 B = *(const uint2*)(sm + Kb + ((ktc * 16 + kh * 8 + nt) * 32 + l) * 8);
                MMA_BF16(sacc[0][nt], A0, B);
                MMA_BF16(sacc[1][nt], A1, B);
            }
        }

        // ---- pack scores to bf16x2 then ex2 on bf16x2 (half the MUFU work) ----
        uint4 pP[2][4];
        #pragma unroll
        for (int mt = 0; mt < 2; mt++) {
            #pragma unroll
            for (int kc = 0; kc < 4; kc++) {
                const int nt0 = 2 * kc, nt1 = 2 * kc + 1;
                pP[mt][kc].x = ex2_bf16x2(pack_bf16x2(sacc[mt][nt0][0], sacc[mt][nt0][1]));
                pP[mt][kc].y = ex2_bf16x2(pack_bf16x2(sacc[mt][nt0][2], sacc[mt][nt0][3]));
                pP[mt][kc].z = ex2_bf16x2(pack_bf16x2(sacc[mt][nt1][0], sacc[mt][nt1][1]));
                pP[mt][kc].w = ex2_bf16x2(pack_bf16x2(sacc[mt][nt1][2], sacc[mt][nt1][3]));
            }
        }

        // ---- O += P V over this warp's 64 keys, all 128 hd; lsum via ones-MMA ----
        const uint32_t Vb = SM_V0 + (t & 1) * 32768;
        #pragma unroll
        for (int kt = 0; kt < 4; kt++) {
            const uint4 A0 = pP[0][kt], A1 = pP[1][kt];
            #pragma unroll
            for (int nt = 0; nt < 16; nt++) {
                uint2 B = *(const uint2*)(sm + Vb + (((kh * 4 + kt) * 16 + nt) * 32 + l) * 8);
                MMA_BF16(oacc[0][nt], A0, B);
                MMA_BF16(oacc[1][nt], A1, B);
            }
            MMA_BF16(lacc[0], A0, Bones);
            MMA_BF16(lacc[1], A1, Bones);
        }
    }

    // ---- publish per-key-half row sums (held by tig==0 lanes: cols 0) ----
    __syncthreads();   // all compute done; smem free for Ob
    float* Ob = (float*)sm;   // [128 hd][stride 132] fp32
    if (tig == 0) {
        #pragma unroll
        for (int mt = 0; mt < 2; mt++) {
            lsum_s[kh][qi * 32 + mt * 16 + gid]     = lacc[mt][0];
            lsum_s[kh][qi * 32 + mt * 16 + gid + 8] = lacc[mt][2];
        }
    }
    if (kh == 0) {
        #pragma unroll
        for (int mt = 0; mt < 2; mt++)
            #pragma unroll
            for (int nt = 0; nt < 16; nt++)
                #pragma unroll
                for (int j = 0; j < 4; j++) {
                    const int q  = qi * 32 + mt * 16 + gid + 8 * (j >> 1);
                    const int hd = nt * 8 + tig * 2 + (j & 1);
                    Ob[hd * 132 + q] = oacc[mt][nt][j];
                }
    }
    __syncthreads();
    if (kh == 1) {
        #pragma unroll
        for (int mt = 0; mt < 2; mt++)
            #pragma unroll
            for (int nt = 0; nt < 16; nt++)
                #pragma unroll
                for (int j = 0; j < 4; j++) {
                    const int q  = qi * 32 + mt * 16 + gid + 8 * (j >> 1);
                    const int hd = nt * 8 + tig * 2 + (j & 1);
                    Ob[hd * 132 + q] += oacc[mt][nt][j];
                }
    }
    __syncthreads();

    const size_t attbase = (size_t)b * 524288;
    #pragma unroll
    for (int it = 0; it < 16; it++) {
        const int slot = tid + it * 256;
        const int lb = slot >> 5, ln = slot & 31;
        const int ntl = lb >> 3, ktl = lb & 7;
        const int g2 = ln >> 2, t2 = ln & 3;
        const int cl = ktl * 16 + 2 * t2;
        const int ql = ntl * 8 + g2;
        const float linv = 1.0f / (lsum_s[0][ql] + lsum_s[1][ql]);
        uint2 o;
        o.x = pack_bf16x2(Ob[cl * 132 + ql] * linv,       Ob[(cl + 1) * 132 + ql] * linv);
        o.y = pack_bf16x2(Ob[(cl + 8) * 132 + ql] * linv, Ob[(cl + 9) * 132 + ql] * linv);
        attf[attbase + ((size_t)(qb * 16 + ntl) * 32 + (h * 8 + ktl)) * 32 + ln] = o;
    }
}

// ---------------- host ----------------
extern "C" void kernel_launch(void* const* d_in, const int* in_sizes, int n_in,
                              void* d_out, int out_size) {
    const float* x      = (const float*)d_in[0];
    const float* gn_w   = (const float*)d_in[1];
    const float* gn_b   = (const float*)d_in[2];
    const float* w_qkv  = (const float*)d_in[3];
    const float* b_qkv  = (const float*)d_in[4];
    const float* w_proj = (const float*)d_in[5];
    const float* b_proj = (const float*)d_in[6];
    float* out = (float*)d_out;

    uint4 *qf_p, *wqf_p, *wpf_p;
    uint2 *kf_p, *vf_p, *xnf_p, *attf_p;
    cudaGetSymbolAddress((void**)&qf_p, g_qf);
    cudaGetSymbolAddress((void**)&kf_p, g_kf);
    cudaGetSymbolAddress((void**)&vf_p, g_vf);
    cudaGetSymbolAddress((void**)&xnf_p, g_xnf);
    cudaGetSymbolAddress((void**)&attf_p, g_attf);
    cudaGetSymbolAddress((void**)&wqf_p, g_wqf);
    cudaGetSymbolAddress((void**)&wpf_p, g_wpf);

    // 1) fused prep (GN stats + weight packing), then GN apply/pack
    prep_kernel<<<1024, 256>>>(x, w_qkv, w_proj, wqf_p, wpf_p);
    gn_apply_kernel<<<dim3(GROUPS, BATCH, GN_SPL), 256>>>(x, gn_w, gn_b, xnf_p);

    // 2) QKV GEMM (128 threads, 64x64 warps) with fused q/k/v fragment epilogue
    cudaFuncSetAttribute(gemm_qkv_kernel, cudaFuncAttributeMaxDynamicSharedMemorySize, QKV_SMEM);
    gemm_qkv_kernel<<<dim3(32, 12, BATCH), 128, QKV_SMEM>>>(wqf_p, xnf_p, b_qkv,
                                                            qf_p, kf_p, vf_p);

    // 3) attention (128-key tiles, register P, bf16x2 exp, MMA lsum)
    cudaFuncSetAttribute(attn_bf16_kernel, cudaFuncAttributeMaxDynamicSharedMemorySize, ATT_SMEM);
    attn_bf16_kernel<<<dim3(L / 128, BATCH * NH), 256, ATT_SMEM>>>(qf_p, kf_p, vf_p, attf_p);

    // 4) proj GEMM (128 threads, 64x64 warps) + bias + residual -> out
    cudaFuncSetAttribute(gemm_bf16_kernel, cudaFuncAttributeMaxDynamicSharedMemorySize, PROJ_SMEM);
    gemm_bf16_kernel<<<dim3(32, 4, BATCH), 128, PROJ_SMEM>>>(wpf_p, attf_p, b_proj, x, out, C);
}